// round 12
// baseline (speedup 1.0000x reference)
#include <cuda_runtime.h>
#include <cuda_fp16.h>

#define B_  2
#define N_  5000
#define C_  256
#define H_  8
#define M_  2500
#define DK_ 32
#define VST 2560   // padded M stride for g_vt, pad stays 0

// ---------------- scratch (device globals; zero-initialized) ---------------
__device__ __half g_xth[B_*C_*N_];    // x^T fp16 (B,C,N)
__device__ __half g_Wqh[C_*C_];
__device__ __half g_Wkh[C_*C_];
__device__ __half g_Wvh[C_*C_];
__device__ __half g_xrh[B_*M_*C_];    // LN output fp16
__device__ __half g_qh [B_*N_*C_];    // Q (pre-scaled by 1/sqrt(32)*log2e)
__device__ __half g_kh [B_*M_*C_];
__device__ __half g_vt [B_*C_*VST];   // V^T (B,C,Mpad)

// ---------------- helpers ---------------------------------------------------
__device__ __forceinline__ unsigned sm_u32(const void* p) {
    return (unsigned)__cvta_generic_to_shared(p);
}
__device__ __forceinline__ void ldsm4(unsigned addr, unsigned& r0, unsigned& r1,
                                      unsigned& r2, unsigned& r3) {
    asm volatile("ldmatrix.sync.aligned.m8n8.x4.shared.b16 {%0,%1,%2,%3}, [%4];"
                 : "=r"(r0), "=r"(r1), "=r"(r2), "=r"(r3) : "r"(addr));
}
__device__ __forceinline__ void mma16816(float* c, unsigned a0, unsigned a1,
                                         unsigned a2, unsigned a3,
                                         unsigned b0, unsigned b1) {
    asm volatile("mma.sync.aligned.m16n8k16.row.col.f32.f16.f16.f32 "
                 "{%0,%1,%2,%3}, {%4,%5,%6,%7}, {%8,%9}, {%0,%1,%2,%3};"
                 : "+f"(c[0]), "+f"(c[1]), "+f"(c[2]), "+f"(c[3])
                 : "r"(a0), "r"(a1), "r"(a2), "r"(a3), "r"(b0), "r"(b1));
}
// fp16-accumulate variant: C/D are 2 regs of packed half2
__device__ __forceinline__ void mma16816h(unsigned& c0, unsigned& c1,
                                          unsigned a0, unsigned a1,
                                          unsigned a2, unsigned a3,
                                          unsigned b0, unsigned b1) {
    asm volatile("mma.sync.aligned.m16n8k16.row.col.f16.f16.f16.f16 "
                 "{%0,%1}, {%2,%3,%4,%5}, {%6,%7}, {%0,%1};"
                 : "+r"(c0), "+r"(c1)
                 : "r"(a0), "r"(a1), "r"(a2), "r"(a3), "r"(b0), "r"(b1));
}
__device__ __forceinline__ unsigned pack2(float a, float b) {
    __half2 h = __floats2half2_rn(a, b);
    return *reinterpret_cast<unsigned*>(&h);
}
__device__ __forceinline__ unsigned h2ex2(unsigned x) {
    unsigned y;
    asm("ex2.approx.f16x2 %0, %1;" : "=r"(y) : "r"(x));
    return y;
}
__device__ __forceinline__ void cp16(void* dst_smem, const void* src, bool pred) {
    unsigned d = sm_u32(dst_smem);
    int sz = pred ? 16 : 0;
    asm volatile("cp.async.cg.shared.global [%0], [%1], 16, %2;"
                 :: "r"(d), "l"(src), "r"(sz));
}
__device__ __forceinline__ void cp_commit() {
    asm volatile("cp.async.commit_group;");
}
template <int NN>
__device__ __forceinline__ void cp_wait() {
    asm volatile("cp.async.wait_group %0;" :: "n"(NN));
}

// ===========================================================================
// Kernel 1: fused x-transpose + W converts
// ===========================================================================
#define TRX_CTAS 2512   // 8 * 157 * 2
__global__ __launch_bounds__(256) void k_pre(const float* __restrict__ x,
                                             const float* __restrict__ Wq,
                                             const float* __restrict__ Wk,
                                             const float* __restrict__ Wv) {
    __shared__ float tile[32][33];
    const int id = blockIdx.x;
    if (id < TRX_CTAS) {
        int c_idx = id & 7;
        int n_idx = (id >> 3) % 157;
        int b     = id / (8 * 157);
        int c0 = c_idx * 32, n0 = n_idx * 32;
        int tx = threadIdx.x & 31, ty = threadIdx.x >> 5;
        #pragma unroll
        for (int i = 0; i < 4; i++) {
            int n = n0 + ty + i * 8;
            tile[ty + i * 8][tx] = (n < N_) ? x[((size_t)b * N_ + n) * C_ + c0 + tx] : 0.f;
        }
        __syncthreads();
        #pragma unroll
        for (int i = 0; i < 4; i++) {
            int n = n0 + tx;
            int c = c0 + ty + i * 8;
            if (n < N_) g_xth[((size_t)b * C_ + c) * N_ + n] = __float2half(tile[tx][ty + i * 8]);
        }
    } else {
        int id2 = id - TRX_CTAS;
        int sel = id2 >> 7;
        int blk = id2 & 127;
        const float* in = (sel == 0) ? Wq : ((sel == 1) ? Wk : Wv);
        __half* out = (sel == 0) ? g_Wqh : ((sel == 1) ? g_Wkh : g_Wvh);
        int i = (blk * 256 + threadIdx.x) * 2;
        float2 v = *(const float2*)(in + i);
        *(__half2*)(out + i) = __floats2half2_rn(v.x, v.y);
    }
}

// ===========================================================================
// Kernel 2: merged [reduce-GEMM + fused LayerNorm] + Q-projection
//   reduce: 32-row x 256-col tiles -> 160 CTAs (was 80) so the long
//   K-loop critical path spreads over more SMs. LN stays fused.
// ===========================================================================
#define RED_CTAS 160     // 2 (b) * 80 (32-row blocks)
#define PQ_CTAS  316
#define RKT 157
#define RED_SMEM 46080   // As 2*2560B + Bs 2*20480B

__device__ void reduce_part(char* dsm, const float* __restrict__ Wc,
                            const float* __restrict__ gamma,
                            const float* __restrict__ beta, int id) {
    __half* As0 = (__half*)dsm;                  // 2 stages x 32*40 halves
    __half* Bs0 = (__half*)(dsm + 5120);         // 2 stages x 256*40 halves

    const int b  = id & 1;
    const int mb = id >> 1;
    const int m0 = mb * 32;
    const int t = threadIdx.x, lane = t & 31, w = t >> 5;
    const int wn = w;                             // 8 warps: warp tile 32m x 32c
    const __half* Bg = g_xth + (size_t)b * C_ * N_;

    const int lr = t >> 2, ls = t & 3;            // A loader (t<128): 32 rows x 4 segs

    float acc[2][4][4];                           // [mf: 2x16 rows][nf: 4x8 cols][q]
    #pragma unroll
    for (int i = 0; i < 2; i++)
        #pragma unroll
        for (int j = 0; j < 4; j++)
            #pragma unroll
            for (int q = 0; q < 4; q++) acc[i][j][q] = 0.f;

    float4 ar[2];
    auto ldgA = [&](int k0) {
        if (t < 128) {
            int gm = m0 + lr, gk = k0 + ls * 8;
            if (gm < M_ && gk + 8 <= N_) {
                const float* p = Wc + (size_t)gm * N_ + gk;
                ar[0] = *(const float4*)(p);
                ar[1] = *(const float4*)(p + 4);
            } else {
                ar[0] = make_float4(0.f, 0.f, 0.f, 0.f);
                ar[1] = make_float4(0.f, 0.f, 0.f, 0.f);
            }
        }
    };
    auto stsA = [&](int buf) {
        if (t < 128) {
            uint4 v;
            v.x = pack2(ar[0].x, ar[0].y); v.y = pack2(ar[0].z, ar[0].w);
            v.z = pack2(ar[1].x, ar[1].y); v.w = pack2(ar[1].z, ar[1].w);
            *(uint4*)(As0 + buf * 1280 + lr * 40 + ls * 8) = v;
        }
    };
    auto cpB = [&](int k0, int buf) {
        #pragma unroll
        for (int i = 0; i < 4; i++) {
            int u = t + 256 * i;
            int r = u >> 2, s = u & 3;
            int gk = k0 + s * 8;
            cp16(Bs0 + buf * 10240 + r * 40 + s * 8,
                 Bg + (size_t)r * N_ + gk, gk + 8 <= N_);
        }
    };

    ldgA(0);
    stsA(0);
    cpB(0, 0);
    cp_commit();

    for (int tt = 0; tt < RKT; tt++) {
        int buf = tt & 1;
        if (tt + 1 < RKT) {
            ldgA((tt + 1) * 32);
            cpB((tt + 1) * 32, buf ^ 1);
        }
        cp_commit();
        cp_wait<1>();
        __syncthreads();

        #pragma unroll
        for (int ks = 0; ks < 2; ks++) {
            unsigned a[2][4];
            #pragma unroll
            for (int mf = 0; mf < 2; mf++) {
                unsigned addr = sm_u32(As0 + buf * 1280 + (mf * 16 + (lane & 15)) * 40
                                       + ks * 16 + ((lane >> 4) << 3));
                ldsm4(addr, a[mf][0], a[mf][1], a[mf][2], a[mf][3]);
            }
            #pragma unroll
            for (int p = 0; p < 2; p++) {
                unsigned b0, b1, b2, b3;
                unsigned addr = sm_u32(Bs0 + buf * 10240 + (wn * 32 + p * 16 + (lane & 15)) * 40
                                       + ks * 16 + ((lane >> 4) << 3));
                ldsm4(addr, b0, b1, b2, b3);
                #pragma unroll
                for (int mf = 0; mf < 2; mf++) {
                    mma16816(acc[mf][2 * p],     a[mf][0], a[mf][1], a[mf][2], a[mf][3], b0, b2);
                    mma16816(acc[mf][2 * p + 1], a[mf][0], a[mf][1], a[mf][2], a[mf][3], b1, b3);
                }
            }
        }
        if (tt + 1 < RKT) stsA(buf ^ 1);
        __syncthreads();
    }

    // ---- fused LayerNorm epilogue (bc drops out) ----
    // rows: rloc = mf*16 + hh*8 + (lane>>2); cols: wn*32 + nf*8 + (lane&3)*2
    float2* red = (float2*)dsm;   // [32 rows][8 warps] partial (sum, sumsq)
    #pragma unroll
    for (int mf = 0; mf < 2; mf++) {
        #pragma unroll
        for (int hh = 0; hh < 2; hh++) {
            float s = 0.f, s2 = 0.f;
            #pragma unroll
            for (int nf = 0; nf < 4; nf++) {
                float v0 = acc[mf][nf][hh * 2 + 0];
                float v1 = acc[mf][nf][hh * 2 + 1];
                s += v0 + v1;
                s2 += v0 * v0 + v1 * v1;
            }
            s  += __shfl_xor_sync(0xffffffffu, s, 1);
            s2 += __shfl_xor_sync(0xffffffffu, s2, 1);
            s  += __shfl_xor_sync(0xffffffffu, s, 2);
            s2 += __shfl_xor_sync(0xffffffffu, s2, 2);
            int rloc = mf * 16 + hh * 8 + (lane >> 2);
            if ((lane & 3) == 0) red[rloc * 8 + wn] = make_float2(s, s2);
        }
    }
    __syncthreads();
    #pragma unroll
    for (int mf = 0; mf < 2; mf++) {
        #pragma unroll
        for (int hh = 0; hh < 2; hh++) {
            int rloc = mf * 16 + hh * 8 + (lane >> 2);
            int r = m0 + rloc;
            float s = 0.f, s2 = 0.f;
            #pragma unroll
            for (int j = 0; j < 8; j++) {
                float2 pp = red[rloc * 8 + j];
                s += pp.x; s2 += pp.y;
            }
            float mu  = s * (1.f / 256.f);
            float var = s2 * (1.f / 256.f) - mu * mu;
            float rs  = rsqrtf(var + 1e-5f);
            if (r < M_) {
                #pragma unroll
                for (int nf = 0; nf < 4; nf++) {
                    int c = wn * 32 + nf * 8 + (lane & 3) * 2;
                    float y0 = gamma[c]     * (acc[mf][nf][hh * 2 + 0] - mu) * rs + beta[c];
                    float y1 = gamma[c + 1] * (acc[mf][nf][hh * 2 + 1] - mu) * rs + beta[c + 1];
                    *(__half2*)(g_xrh + ((size_t)b * M_ + r) * C_ + c) = __floats2half2_rn(y0, y1);
                }
            }
        }
    }
}

__device__ void projQ_part(char* dsm, const float* __restrict__ x,
                           const float* __restrict__ bq, int id) {
    __half* As = (__half*)dsm;
    __half* Bs = (__half*)(dsm + 10240);

    const int r0 = (id >> 2) * 128;
    const int c0 = (id & 3) * 64;
    const int t = threadIdx.x, lane = t & 31, w = t >> 5;
    const int wm = w >> 1, wn = w & 1;
    const int R = B_ * N_;
    const float qscale = 0.17677669529663687f * 1.4426950408889634f;

    float acc[2][4][4];
    #pragma unroll
    for (int i = 0; i < 2; i++)
        #pragma unroll
        for (int j = 0; j < 4; j++)
            #pragma unroll
            for (int q = 0; q < 4; q++) acc[i][j][q] = 0.f;

    for (int k0 = 0; k0 < C_; k0 += 32) {
        #pragma unroll
        for (int i = 0; i < 2; i++) {
            int u = t + 256 * i;
            int r = u >> 2, s = u & 3;
            int gr = r0 + r;
            uint4 v = make_uint4(0, 0, 0, 0);
            if (gr < R) {
                const float* p = x + (size_t)gr * C_ + k0 + s * 8;
                float4 f0 = *(const float4*)(p);
                float4 f1 = *(const float4*)(p + 4);
                v.x = pack2(f0.x, f0.y); v.y = pack2(f0.z, f0.w);
                v.z = pack2(f1.x, f1.y); v.w = pack2(f1.z, f1.w);
            }
            *(uint4*)(As + r * 40 + s * 8) = v;
        }
        {
            int r = t >> 2, s = t & 3;
            uint4 v = *(const uint4*)(g_Wqh + (size_t)(c0 + r) * C_ + k0 + s * 8);
            *(uint4*)(Bs + r * 40 + s * 8) = v;
        }
        __syncthreads();
        #pragma unroll
        for (int ks = 0; ks < 2; ks++) {
            unsigned a[2][4];
            #pragma unroll
            for (int mf = 0; mf < 2; mf++) {
                unsigned addr = sm_u32(As + (wm * 32 + mf * 16 + (lane & 15)) * 40
                                       + ks * 16 + ((lane >> 4) << 3));
                ldsm4(addr, a[mf][0], a[mf][1], a[mf][2], a[mf][3]);
            }
            unsigned bf[2][4];
            #pragma unroll
            for (int p = 0; p < 2; p++) {
                unsigned addr = sm_u32(Bs + (wn * 32 + p * 16 + (lane & 15)) * 40
                                       + ks * 16 + ((lane >> 4) << 3));
                ldsm4(addr, bf[p][0], bf[p][1], bf[p][2], bf[p][3]);
            }
            #pragma unroll
            for (int mf = 0; mf < 2; mf++)
                #pragma unroll
                for (int p = 0; p < 2; p++) {
                    mma16816(acc[mf][2 * p],     a[mf][0], a[mf][1], a[mf][2], a[mf][3], bf[p][0], bf[p][2]);
                    mma16816(acc[mf][2 * p + 1], a[mf][0], a[mf][1], a[mf][2], a[mf][3], bf[p][1], bf[p][3]);
                }
        }
        __syncthreads();
    }
    #pragma unroll
    for (int mf = 0; mf < 2; mf++) {
        #pragma unroll
        for (int hh = 0; hh < 2; hh++) {
            int r = r0 + wm * 32 + mf * 16 + (lane >> 2) + hh * 8;
            if (r >= R) continue;
            #pragma unroll
            for (int nf = 0; nf < 4; nf++) {
                int c = c0 + wn * 32 + nf * 8 + (lane & 3) * 2;
                float v0 = (acc[mf][nf][hh * 2 + 0] + bq[c])     * qscale;
                float v1 = (acc[mf][nf][hh * 2 + 1] + bq[c + 1]) * qscale;
                *(__half2*)(g_qh + (size_t)r * C_ + c) = __floats2half2_rn(v0, v1);
            }
        }
    }
}

__global__ __launch_bounds__(256) void k_red_projQ(const float* __restrict__ Wc,
                                                   const float* __restrict__ gamma,
                                                   const float* __restrict__ beta,
                                                   const float* __restrict__ x,
                                                   const float* __restrict__ bq) {
    extern __shared__ __align__(16) char dsm[];
    if (blockIdx.x < RED_CTAS) reduce_part(dsm, Wc, gamma, beta, blockIdx.x);
    else                       projQ_part(dsm, x, bq, blockIdx.x - RED_CTAS);
}

// ===========================================================================
// Kernel 3: K and V projections, 2-stage cp.async pipeline
// ===========================================================================
#define KV_CTAS 160
__global__ __launch_bounds__(256) void k_projKV(const float* __restrict__ bk,
                                                const float* __restrict__ bv) {
    __shared__ __align__(16) __half As[2][128 * 40];
    __shared__ __align__(16) __half Bs[2][64 * 40];

    const int id = blockIdx.x;
    const int mode = (id < KV_CTAS) ? 1 : 2;
    const int rid = (mode == 1) ? id : id - KV_CTAS;
    const int r0 = (rid >> 2) * 128;
    const int c0 = (rid & 3) * 64;
    const __half* W   = (mode == 1) ? g_Wkh : g_Wvh;
    const float* bias = (mode == 1) ? bk : bv;
    const int R = B_ * M_;

    const int t = threadIdx.x, lane = t & 31, w = t >> 5;
    const int wm = w >> 1, wn = w & 1;

    float acc[2][4][4];
    #pragma unroll
    for (int i = 0; i < 2; i++)
        #pragma unroll
        for (int j = 0; j < 4; j++)
            #pragma unroll
            for (int q = 0; q < 4; q++) acc[i][j][q] = 0.f;

    auto load_stage = [&](int k0, int buf) {
        #pragma unroll
        for (int i = 0; i < 2; i++) {
            int u = t + 256 * i;
            int r = u >> 2, s = u & 3;
            cp16(&As[buf][r * 40 + s * 8],
                 g_xrh + (size_t)(r0 + r) * C_ + k0 + s * 8, r0 + r < R);
        }
        {
            int r = t >> 2, s = t & 3;
            cp16(&Bs[buf][r * 40 + s * 8],
                 W + (size_t)(c0 + r) * C_ + k0 + s * 8, true);
        }
    };

    load_stage(0, 0);
    cp_commit();

    for (int it = 0; it < 8; it++) {
        int buf = it & 1;
        if (it + 1 < 8) load_stage((it + 1) * 32, buf ^ 1);
        cp_commit();
        cp_wait<1>();
        __syncthreads();
        #pragma unroll
        for (int ks = 0; ks < 2; ks++) {
            unsigned a[2][4];
            #pragma unroll
            for (int mf = 0; mf < 2; mf++) {
                unsigned addr = sm_u32(&As[buf][(wm * 32 + mf * 16 + (lane & 15)) * 40
                                       + ks * 16 + ((lane >> 4) << 3)]);
                ldsm4(addr, a[mf][0], a[mf][1], a[mf][2], a[mf][3]);
            }
            unsigned bf[2][4];
            #pragma unroll
            for (int p = 0; p < 2; p++) {
                unsigned addr = sm_u32(&Bs[buf][(wn * 32 + p * 16 + (lane & 15)) * 40
                                       + ks * 16 + ((lane >> 4) << 3)]);
                ldsm4(addr, bf[p][0], bf[p][1], bf[p][2], bf[p][3]);
            }
            #pragma unroll
            for (int mf = 0; mf < 2; mf++)
                #pragma unroll
                for (int p = 0; p < 2; p++) {
                    mma16816(acc[mf][2 * p],     a[mf][0], a[mf][1], a[mf][2], a[mf][3], bf[p][0], bf[p][2]);
                    mma16816(acc[mf][2 * p + 1], a[mf][0], a[mf][1], a[mf][2], a[mf][3], bf[p][1], bf[p][3]);
                }
        }
        __syncthreads();
    }
    #pragma unroll
    for (int mf = 0; mf < 2; mf++) {
        #pragma unroll
        for (int hh = 0; hh < 2; hh++) {
            int r = r0 + wm * 32 + mf * 16 + (lane >> 2) + hh * 8;
            if (r >= R) continue;
            #pragma unroll
            for (int nf = 0; nf < 4; nf++) {
                int c = c0 + wn * 32 + nf * 8 + (lane & 3) * 2;
                float v0 = acc[mf][nf][hh * 2 + 0] + bias[c];
                float v1 = acc[mf][nf][hh * 2 + 1] + bias[c + 1];
                if (mode == 1) {
                    *(__half2*)(g_kh + (size_t)r * C_ + c) = __floats2half2_rn(v0, v1);
                } else {
                    int bb = r / M_, m = r - bb * M_;
                    g_vt[((size_t)bb * C_ + c)     * VST + m] = __float2half(v0);
                    g_vt[((size_t)bb * C_ + c + 1) * VST + m] = __float2half(v1);
                }
            }
        }
    }
}

// ===========================================================================
// Kernel 4: flash attention — QK fp16-acc MMA (C-frag == packed half2 P),
// ex2 in place, PV/l fp32-acc. (unchanged from best config)
// ===========================================================================
#define NT2 20
#define ONES2 0x3C003C00u
#define NEGBIG2 0xDF00DF00u   // half2(-448, -448): ex2 -> 0
__global__ __launch_bounds__(128, 4) void k_attn(float* __restrict__ out) {
    __shared__ __half Ks[2][128 * 40];   // 10240 B each
    __shared__ __half Vt[2][32 * 136];   //  8704 B each

    const int b = blockIdx.z, h = blockIdx.y;
    const int t = threadIdx.x, lane = t & 31, w = t >> 5;
    const int n0 = blockIdx.x * 128;

    // stage Q (128 x 32) through Ks[0], then hold fragments in registers
    #pragma unroll
    for (int i = 0; i < 4; i++) {
        int u = t + 128 * i;
        int r = u >> 2, s = u & 3;
        cp16(&Ks[0][r * 40 + s * 8],
             g_qh + ((size_t)(b * N_ + n0 + r)) * C_ + h * 32 + s * 8, n0 + r < N_);
    }
    cp_commit();
    cp_wait<0>();
    __syncthreads();
    unsigned qa[2][2][4];   // [mf][ks]
    #pragma unroll
    for (int mf = 0; mf < 2; mf++)
        #pragma unroll
        for (int ks = 0; ks < 2; ks++) {
            unsigned addr = sm_u32(&Ks[0][(w * 32 + mf * 16 + (lane & 15)) * 40
                                   + ks * 16 + ((lane >> 4) << 3)]);
            ldsm4(addr, qa[mf][ks][0], qa[mf][ks][1], qa[mf][ks][2], qa[mf][ks][3]);
        }
    __syncthreads();   // all warps done with Q before Ks[0] is recycled

    const __half* Kg = g_kh + ((size_t)b * M_) * C_ + h * 32;
    const __half* Vg = g_vt + ((size_t)(b * C_ + h * 32)) * VST;
    auto load_kv = [&](int tile, int buf) {
        int m0 = tile * 128;
        #pragma unroll
        for (int i = 0; i < 4; i++) {
            int u = t + 128 * i;
            int r = u >> 2, s = u & 3;
            cp16(&Ks[buf][r * 40 + s * 8], Kg + (size_t)(m0 + r) * C_ + s * 8, m0 + r < M_);
        }
        #pragma unroll
        for (int i = 0; i < 4; i++) {
            int u = t + 128 * i;
            int r = u >> 4, s = u & 15;
            cp16(&Vt[buf][r * 136 + s * 8], Vg + (size_t)r * VST + m0 + s * 8, true);
        }
    };

    load_kv(0, 0);
    cp_commit();

    float lacc[2][4];
    #pragma unroll
    for (int mf = 0; mf < 2; mf++)
        #pragma unroll
        for (int j = 0; j < 4; j++) lacc[mf][j] = 0.f;
    float oacc[2][4][4];
    #pragma unroll
    for (int mf = 0; mf < 2; mf++)
        #pragma unroll
        for (int i = 0; i < 4; i++)
            #pragma unroll
            for (int j = 0; j < 4; j++) oacc[mf][i][j] = 0.f;

    const unsigned lane_off = (lane & 15) * 40 + ((lane >> 4) << 3);

    for (int tile = 0; tile < NT2; tile++) {
        const int buf = tile & 1;
        if (tile + 1 < NT2) load_kv(tile + 1, buf ^ 1);
        cp_commit();
        cp_wait<1>();
        __syncthreads();

        #pragma unroll
        for (int half = 0; half < 2; half++) {
            unsigned ph[2][8][2];
            // QK with fp16 accumulation: C fragment {c01, c23} is the packed P
            #pragma unroll
            for (int p = 0; p < 4; p++) {
                unsigned ch[2][2][2];   // [mf][f][reg]
                #pragma unroll
                for (int mf = 0; mf < 2; mf++)
                    #pragma unroll
                    for (int f = 0; f < 2; f++) {
                        ch[mf][f][0] = 0u; ch[mf][f][1] = 0u;
                    }
                #pragma unroll
                for (int ks = 0; ks < 2; ks++) {
                    unsigned bb0, bb1, bb2, bb3;
                    unsigned addr = sm_u32(&Ks[buf][(half * 64 + p * 16) * 40 + ks * 16]) + lane_off * 2;
                    ldsm4(addr, bb0, bb1, bb2, bb3);
                    #pragma unroll
                    for (int mf = 0; mf < 2; mf++) {
                        mma16816h(ch[mf][0][0], ch[mf][0][1], qa[mf][ks][0], qa[mf][ks][1],
                                  qa[mf][ks][2], qa[mf][ks][3], bb0, bb2);
                        mma16816h(ch[mf][1][0], ch[mf][1][1], qa[mf][ks][0], qa[mf][ks][1],
                                  qa[mf][ks][2], qa[mf][ks][3], bb1, bb3);
                    }
                }
                // mask tail keys (M_ even => key pairs never straddle the edge)
                if (tile == NT2 - 1) {
                    #pragma unroll
                    for (int f = 0; f < 2; f++) {
                        int key = tile * 128 + half * 64 + (p * 2 + f) * 8 + (lane & 3) * 2;
                        if (key >= M_) {
                            #pragma unroll
                            for (int mf = 0; mf < 2; mf++) {
                                ch[mf][f][0] = NEGBIG2; ch[mf][f][1] = NEGBIG2;
                            }
                        }
                    }
                }
                #pragma unroll
                for (int mf = 0; mf < 2; mf++)
                    #pragma unroll
                    for (int f = 0; f < 2; f++) {
                        ph[mf][p * 2 + f][0] = h2ex2(ch[mf][f][0]);
                        ph[mf][p * 2 + f][1] = h2ex2(ch[mf][f][1]);
                    }
            }
            // O += P V ; l += P @ ones  (fp32 accumulate)
            #pragma unroll
            for (int kk = 0; kk < 4; kk++) {
                #pragma unroll
                for (int mf = 0; mf < 2; mf++)
                    mma16816(lacc[mf], ph[mf][2 * kk][0], ph[mf][2 * kk][1],
                             ph[mf][2 * kk + 1][0], ph[mf][2 * kk + 1][1], ONES2, ONES2);
                #pragma unroll
                for (int p = 0; p < 2; p++) {
                    unsigned bb0, bb1, bb2, bb3;
                    unsigned addr = sm_u32(&Vt[buf][(p * 16 + (lane & 15)) * 136
                                           + (half * 4 + kk) * 16 + ((lane >> 4) << 3)]);
                    ldsm4(addr, bb0, bb1, bb2, bb3);
                    #pragma unroll
                    for (int mf = 0; mf < 2; mf++) {
                        mma16816(oacc[mf][2 * p],     ph[mf][2 * kk][0], ph[mf][2 * kk][1],
                                 ph[mf][2 * kk + 1][0], ph[mf][2 * kk + 1][1], bb0, bb2);
                        mma16816(oacc[mf][2 * p + 1], ph[mf][2 * kk][0], ph[mf][2 * kk][1],
                                 ph[mf][2 * kk + 1][0], ph[mf][2 * kk + 1][1], bb1, bb3);
                    }
                }
            }
        }
        __syncthreads();
    }

    #pragma unroll
    for (int mf = 0; mf < 2; mf++) {
        float inv0 = 1.f / lacc[mf][0];
        float inv1 = 1.f / lacc[mf][2];
        int r = n0 + w * 32 + mf * 16 + (lane >> 2);
        #pragma unroll
        for (int nf = 0; nf < 4; nf++) {
            int d = h * 32 + nf * 8 + (lane & 3) * 2;
            if (r < N_) {
                *(float2*)(out + ((size_t)(b * N_ + r)) * C_ + d) =
                    make_float2(oacc[mf][nf][0] * inv0, oacc[mf][nf][1] * inv0);
            }
            if (r + 8 < N_) {
                *(float2*)(out + ((size_t)(b * N_ + r + 8)) * C_ + d) =
                    make_float2(oacc[mf][nf][2] * inv1, oacc[mf][nf][3] * inv1);
            }
        }
    }
}

// ---------------------------------------------------------------------------
extern "C" void kernel_launch(void* const* d_in, const int* in_sizes, int n_in,
                              void* d_out, int out_size) {
    (void)in_sizes; (void)n_in; (void)out_size;
    const float* x     = (const float*)d_in[0];
    const float* Wq    = (const float*)d_in[1];
    const float* bq    = (const float*)d_in[2];
    const float* Wk    = (const float*)d_in[3];
    const float* bk    = (const float*)d_in[4];
    const float* Wv    = (const float*)d_in[5];
    const float* bv    = (const float*)d_in[6];
    const float* Wc    = (const float*)d_in[7];
    const float* gamma = (const float*)d_in[9];
    const float* beta  = (const float*)d_in[10];
    float* out = (float*)d_out;

    static bool attr_done = false;
    if (!attr_done) {
        cudaFuncSetAttribute(k_red_projQ, cudaFuncAttributeMaxDynamicSharedMemorySize,
                             RED_SMEM);
        attr_done = true;
    }

    k_pre<<<TRX_CTAS + 384, 256>>>(x, Wq, Wk, Wv);
    k_red_projQ<<<RED_CTAS + PQ_CTAS, 256, RED_SMEM>>>(Wc, gamma, beta, x, bq);
    k_projKV<<<2 * KV_CTAS, 256>>>(bk, bv);
    dim3 ga((N_ + 127) / 128, H_, B_);
    k_attn<<<ga, 128>>>(out);
}

// round 13
// speedup vs baseline: 1.0296x; 1.0296x over previous
#include <cuda_runtime.h>
#include <cuda_fp16.h>

#define B_  2
#define N_  5000
#define C_  256
#define H_  8
#define M_  2500
#define DK_ 32
#define VST 2560   // padded M stride for g_vt, pad stays 0

// ---------------- scratch (device globals; zero-initialized) ---------------
__device__ __half g_xth[B_*C_*N_];    // x^T fp16 (B,C,N)
__device__ __half g_Wqh[C_*C_];
__device__ __half g_Wkh[C_*C_];
__device__ __half g_Wvh[C_*C_];
__device__ __half g_xrh[B_*M_*C_];    // LN output fp16
__device__ __half g_qh [B_*N_*C_];    // Q (pre-scaled by 1/sqrt(32)*log2e)
__device__ __half g_kh [B_*M_*C_];
__device__ __half g_vt [B_*C_*VST];   // V^T (B,C,Mpad)

// ---------------- helpers ---------------------------------------------------
__device__ __forceinline__ unsigned sm_u32(const void* p) {
    return (unsigned)__cvta_generic_to_shared(p);
}
__device__ __forceinline__ void ldsm4(unsigned addr, unsigned& r0, unsigned& r1,
                                      unsigned& r2, unsigned& r3) {
    asm volatile("ldmatrix.sync.aligned.m8n8.x4.shared.b16 {%0,%1,%2,%3}, [%4];"
                 : "=r"(r0), "=r"(r1), "=r"(r2), "=r"(r3) : "r"(addr));
}
__device__ __forceinline__ void mma16816(float* c, unsigned a0, unsigned a1,
                                         unsigned a2, unsigned a3,
                                         unsigned b0, unsigned b1) {
    asm volatile("mma.sync.aligned.m16n8k16.row.col.f32.f16.f16.f32 "
                 "{%0,%1,%2,%3}, {%4,%5,%6,%7}, {%8,%9}, {%0,%1,%2,%3};"
                 : "+f"(c[0]), "+f"(c[1]), "+f"(c[2]), "+f"(c[3])
                 : "r"(a0), "r"(a1), "r"(a2), "r"(a3), "r"(b0), "r"(b1));
}
// fp16-accumulate variant: C/D are 2 regs of packed half2
__device__ __forceinline__ void mma16816h(unsigned& c0, unsigned& c1,
                                          unsigned a0, unsigned a1,
                                          unsigned a2, unsigned a3,
                                          unsigned b0, unsigned b1) {
    asm volatile("mma.sync.aligned.m16n8k16.row.col.f16.f16.f16.f16 "
                 "{%0,%1}, {%2,%3,%4,%5}, {%6,%7}, {%0,%1};"
                 : "+r"(c0), "+r"(c1)
                 : "r"(a0), "r"(a1), "r"(a2), "r"(a3), "r"(b0), "r"(b1));
}
__device__ __forceinline__ unsigned pack2(float a, float b) {
    __half2 h = __floats2half2_rn(a, b);
    return *reinterpret_cast<unsigned*>(&h);
}
__device__ __forceinline__ unsigned h2ex2(unsigned x) {
    unsigned y;
    asm("ex2.approx.f16x2 %0, %1;" : "=r"(y) : "r"(x));
    return y;
}
__device__ __forceinline__ unsigned hadd2u(unsigned a, unsigned b) {
    unsigned c;
    asm("add.f16x2 %0, %1, %2;" : "=r"(c) : "r"(a), "r"(b));
    return c;
}
__device__ __forceinline__ void cp16(void* dst_smem, const void* src, bool pred) {
    unsigned d = sm_u32(dst_smem);
    int sz = pred ? 16 : 0;
    asm volatile("cp.async.cg.shared.global [%0], [%1], 16, %2;"
                 :: "r"(d), "l"(src), "r"(sz));
}
__device__ __forceinline__ void cp_commit() {
    asm volatile("cp.async.commit_group;");
}
template <int NN>
__device__ __forceinline__ void cp_wait() {
    asm volatile("cp.async.wait_group %0;" :: "n"(NN));
}

// ===========================================================================
// Kernel 1: fused x-transpose + W converts
// ===========================================================================
#define TRX_CTAS 2512   // 8 * 157 * 2
__global__ __launch_bounds__(256) void k_pre(const float* __restrict__ x,
                                             const float* __restrict__ Wq,
                                             const float* __restrict__ Wk,
                                             const float* __restrict__ Wv) {
    __shared__ float tile[32][33];
    const int id = blockIdx.x;
    if (id < TRX_CTAS) {
        int c_idx = id & 7;
        int n_idx = (id >> 3) % 157;
        int b     = id / (8 * 157);
        int c0 = c_idx * 32, n0 = n_idx * 32;
        int tx = threadIdx.x & 31, ty = threadIdx.x >> 5;
        #pragma unroll
        for (int i = 0; i < 4; i++) {
            int n = n0 + ty + i * 8;
            tile[ty + i * 8][tx] = (n < N_) ? x[((size_t)b * N_ + n) * C_ + c0 + tx] : 0.f;
        }
        __syncthreads();
        #pragma unroll
        for (int i = 0; i < 4; i++) {
            int n = n0 + tx;
            int c = c0 + ty + i * 8;
            if (n < N_) g_xth[((size_t)b * C_ + c) * N_ + n] = __float2half(tile[tx][ty + i * 8]);
        }
    } else {
        int id2 = id - TRX_CTAS;
        int sel = id2 >> 7;
        int blk = id2 & 127;
        const float* in = (sel == 0) ? Wq : ((sel == 1) ? Wk : Wv);
        __half* out = (sel == 0) ? g_Wqh : ((sel == 1) ? g_Wkh : g_Wvh);
        int i = (blk * 256 + threadIdx.x) * 2;
        float2 v = *(const float2*)(in + i);
        *(__half2*)(out + i) = __floats2half2_rn(v.x, v.y);
    }
}

// ===========================================================================
// Kernel 2: merged [reduce-GEMM + fused LayerNorm] + Q-projection
//   (R11 configuration: 64-row x 256-col reduce tiles, 80 CTAs)
// ===========================================================================
#define RED_CTAS 80
#define PQ_CTAS  316
#define RKT 157
#define RED_SMEM 51200

__device__ void reduce_part(char* dsm, const float* __restrict__ Wc,
                            const float* __restrict__ gamma,
                            const float* __restrict__ beta, int id) {
    __half* As0 = (__half*)dsm;                  // 2 stages x 64*40
    __half* Bs0 = (__half*)(dsm + 10240);        // 2 stages x 256*40

    const int b  = id & 1;
    const int mb = id >> 1;
    const int m0 = mb * 64;
    const int t = threadIdx.x, lane = t & 31, w = t >> 5;
    const int wm = w >> 2, wn = w & 3;
    const __half* Bg = g_xth + (size_t)b * C_ * N_;

    const int lr = t >> 2, ls = t & 3;

    float acc[2][8][4];
    #pragma unroll
    for (int i = 0; i < 2; i++)
        #pragma unroll
        for (int j = 0; j < 8; j++)
            #pragma unroll
            for (int q = 0; q < 4; q++) acc[i][j][q] = 0.f;

    float4 ar[2];
    auto ldgA = [&](int k0) {
        int gm = m0 + lr, gk = k0 + ls * 8;
        if (gm < M_ && gk + 8 <= N_) {
            const float* p = Wc + (size_t)gm * N_ + gk;
            ar[0] = *(const float4*)(p);
            ar[1] = *(const float4*)(p + 4);
        } else {
            ar[0] = make_float4(0.f, 0.f, 0.f, 0.f);
            ar[1] = make_float4(0.f, 0.f, 0.f, 0.f);
        }
    };
    auto stsA = [&](int buf) {
        uint4 v;
        v.x = pack2(ar[0].x, ar[0].y); v.y = pack2(ar[0].z, ar[0].w);
        v.z = pack2(ar[1].x, ar[1].y); v.w = pack2(ar[1].z, ar[1].w);
        *(uint4*)(As0 + buf * 2560 + lr * 40 + ls * 8) = v;
    };
    auto cpB = [&](int k0, int buf) {
        #pragma unroll
        for (int i = 0; i < 4; i++) {
            int u = t + 256 * i;
            int r = u >> 2, s = u & 3;
            int gk = k0 + s * 8;
            cp16(Bs0 + buf * 10240 + r * 40 + s * 8,
                 Bg + (size_t)r * N_ + gk, gk + 8 <= N_);
        }
    };

    ldgA(0);
    stsA(0);
    cpB(0, 0);
    cp_commit();

    for (int tt = 0; tt < RKT; tt++) {
        int buf = tt & 1;
        if (tt + 1 < RKT) {
            ldgA((tt + 1) * 32);
            cpB((tt + 1) * 32, buf ^ 1);
        }
        cp_commit();
        cp_wait<1>();
        __syncthreads();

        #pragma unroll
        for (int ks = 0; ks < 2; ks++) {
            unsigned a[2][4];
            #pragma unroll
            for (int mf = 0; mf < 2; mf++) {
                unsigned addr = sm_u32(As0 + buf * 2560 + (wm * 32 + mf * 16 + (lane & 15)) * 40
                                       + ks * 16 + ((lane >> 4) << 3));
                ldsm4(addr, a[mf][0], a[mf][1], a[mf][2], a[mf][3]);
            }
            #pragma unroll
            for (int p = 0; p < 4; p++) {
                unsigned b0, b1, b2, b3;
                unsigned addr = sm_u32(Bs0 + buf * 10240 + (wn * 64 + p * 16 + (lane & 15)) * 40
                                       + ks * 16 + ((lane >> 4) << 3));
                ldsm4(addr, b0, b1, b2, b3);
                #pragma unroll
                for (int mf = 0; mf < 2; mf++) {
                    mma16816(acc[mf][2 * p],     a[mf][0], a[mf][1], a[mf][2], a[mf][3], b0, b2);
                    mma16816(acc[mf][2 * p + 1], a[mf][0], a[mf][1], a[mf][2], a[mf][3], b1, b3);
                }
            }
        }
        if (tt + 1 < RKT) stsA(buf ^ 1);
        __syncthreads();
    }

    // ---- fused LayerNorm epilogue (bc drops out) ----
    float2* red = (float2*)dsm;
    #pragma unroll
    for (int mf = 0; mf < 2; mf++) {
        #pragma unroll
        for (int hh = 0; hh < 2; hh++) {
            float s = 0.f, s2 = 0.f;
            #pragma unroll
            for (int nf = 0; nf < 8; nf++) {
                float v0 = acc[mf][nf][hh * 2 + 0];
                float v1 = acc[mf][nf][hh * 2 + 1];
                s += v0 + v1;
                s2 += v0 * v0 + v1 * v1;
            }
            s  += __shfl_xor_sync(0xffffffffu, s, 1);
            s2 += __shfl_xor_sync(0xffffffffu, s2, 1);
            s  += __shfl_xor_sync(0xffffffffu, s, 2);
            s2 += __shfl_xor_sync(0xffffffffu, s2, 2);
            int rloc = wm * 32 + mf * 16 + (lane >> 2) + hh * 8;
            if ((lane & 3) == 0) red[rloc * 4 + wn] = make_float2(s, s2);
        }
    }
    __syncthreads();
    #pragma unroll
    for (int mf = 0; mf < 2; mf++) {
        #pragma unroll
        for (int hh = 0; hh < 2; hh++) {
            int rloc = wm * 32 + mf * 16 + (lane >> 2) + hh * 8;
            int r = m0 + rloc;
            float2 p0 = red[rloc * 4 + 0], p1 = red[rloc * 4 + 1];
            float2 p2 = red[rloc * 4 + 2], p3 = red[rloc * 4 + 3];
            float s  = p0.x + p1.x + p2.x + p3.x;
            float s2 = p0.y + p1.y + p2.y + p3.y;
            float mu  = s * (1.f / 256.f);
            float var = s2 * (1.f / 256.f) - mu * mu;
            float rs  = rsqrtf(var + 1e-5f);
            if (r < M_) {
                #pragma unroll
                for (int nf = 0; nf < 8; nf++) {
                    int c = wn * 64 + nf * 8 + (lane & 3) * 2;
                    float y0 = gamma[c]     * (acc[mf][nf][hh * 2 + 0] - mu) * rs + beta[c];
                    float y1 = gamma[c + 1] * (acc[mf][nf][hh * 2 + 1] - mu) * rs + beta[c + 1];
                    *(__half2*)(g_xrh + ((size_t)b * M_ + r) * C_ + c) = __floats2half2_rn(y0, y1);
                }
            }
        }
    }
}

__device__ void projQ_part(char* dsm, const float* __restrict__ x,
                           const float* __restrict__ bq, int id) {
    __half* As = (__half*)dsm;
    __half* Bs = (__half*)(dsm + 10240);

    const int r0 = (id >> 2) * 128;
    const int c0 = (id & 3) * 64;
    const int t = threadIdx.x, lane = t & 31, w = t >> 5;
    const int wm = w >> 1, wn = w & 1;
    const int R = B_ * N_;
    const float qscale = 0.17677669529663687f * 1.4426950408889634f;

    float acc[2][4][4];
    #pragma unroll
    for (int i = 0; i < 2; i++)
        #pragma unroll
        for (int j = 0; j < 4; j++)
            #pragma unroll
            for (int q = 0; q < 4; q++) acc[i][j][q] = 0.f;

    for (int k0 = 0; k0 < C_; k0 += 32) {
        #pragma unroll
        for (int i = 0; i < 2; i++) {
            int u = t + 256 * i;
            int r = u >> 2, s = u & 3;
            int gr = r0 + r;
            uint4 v = make_uint4(0, 0, 0, 0);
            if (gr < R) {
                const float* p = x + (size_t)gr * C_ + k0 + s * 8;
                float4 f0 = *(const float4*)(p);
                float4 f1 = *(const float4*)(p + 4);
                v.x = pack2(f0.x, f0.y); v.y = pack2(f0.z, f0.w);
                v.z = pack2(f1.x, f1.y); v.w = pack2(f1.z, f1.w);
            }
            *(uint4*)(As + r * 40 + s * 8) = v;
        }
        {
            int r = t >> 2, s = t & 3;
            uint4 v = *(const uint4*)(g_Wqh + (size_t)(c0 + r) * C_ + k0 + s * 8);
            *(uint4*)(Bs + r * 40 + s * 8) = v;
        }
        __syncthreads();
        #pragma unroll
        for (int ks = 0; ks < 2; ks++) {
            unsigned a[2][4];
            #pragma unroll
            for (int mf = 0; mf < 2; mf++) {
                unsigned addr = sm_u32(As + (wm * 32 + mf * 16 + (lane & 15)) * 40
                                       + ks * 16 + ((lane >> 4) << 3));
                ldsm4(addr, a[mf][0], a[mf][1], a[mf][2], a[mf][3]);
            }
            unsigned bf[2][4];
            #pragma unroll
            for (int p = 0; p < 2; p++) {
                unsigned addr = sm_u32(Bs + (wn * 32 + p * 16 + (lane & 15)) * 40
                                       + ks * 16 + ((lane >> 4) << 3));
                ldsm4(addr, bf[p][0], bf[p][1], bf[p][2], bf[p][3]);
            }
            #pragma unroll
            for (int mf = 0; mf < 2; mf++)
                #pragma unroll
                for (int p = 0; p < 2; p++) {
                    mma16816(acc[mf][2 * p],     a[mf][0], a[mf][1], a[mf][2], a[mf][3], bf[p][0], bf[p][2]);
                    mma16816(acc[mf][2 * p + 1], a[mf][0], a[mf][1], a[mf][2], a[mf][3], bf[p][1], bf[p][3]);
                }
        }
        __syncthreads();
    }
    #pragma unroll
    for (int mf = 0; mf < 2; mf++) {
        #pragma unroll
        for (int hh = 0; hh < 2; hh++) {
            int r = r0 + wm * 32 + mf * 16 + (lane >> 2) + hh * 8;
            if (r >= R) continue;
            #pragma unroll
            for (int nf = 0; nf < 4; nf++) {
                int c = c0 + wn * 32 + nf * 8 + (lane & 3) * 2;
                float v0 = (acc[mf][nf][hh * 2 + 0] + bq[c])     * qscale;
                float v1 = (acc[mf][nf][hh * 2 + 1] + bq[c + 1]) * qscale;
                *(__half2*)(g_qh + (size_t)r * C_ + c) = __floats2half2_rn(v0, v1);
            }
        }
    }
}

__global__ __launch_bounds__(256) void k_red_projQ(const float* __restrict__ Wc,
                                                   const float* __restrict__ gamma,
                                                   const float* __restrict__ beta,
                                                   const float* __restrict__ x,
                                                   const float* __restrict__ bq) {
    extern __shared__ __align__(16) char dsm[];
    if (blockIdx.x < RED_CTAS) reduce_part(dsm, Wc, gamma, beta, blockIdx.x);
    else                       projQ_part(dsm, x, bq, blockIdx.x - RED_CTAS);
}

// ===========================================================================
// Kernel 3: K and V projections, 2-stage cp.async pipeline
// ===========================================================================
#define KV_CTAS 160
__global__ __launch_bounds__(256) void k_projKV(const float* __restrict__ bk,
                                                const float* __restrict__ bv) {
    __shared__ __align__(16) __half As[2][128 * 40];
    __shared__ __align__(16) __half Bs[2][64 * 40];

    const int id = blockIdx.x;
    const int mode = (id < KV_CTAS) ? 1 : 2;
    const int rid = (mode == 1) ? id : id - KV_CTAS;
    const int r0 = (rid >> 2) * 128;
    const int c0 = (rid & 3) * 64;
    const __half* W   = (mode == 1) ? g_Wkh : g_Wvh;
    const float* bias = (mode == 1) ? bk : bv;
    const int R = B_ * M_;

    const int t = threadIdx.x, lane = t & 31, w = t >> 5;
    const int wm = w >> 1, wn = w & 1;

    float acc[2][4][4];
    #pragma unroll
    for (int i = 0; i < 2; i++)
        #pragma unroll
        for (int j = 0; j < 4; j++)
            #pragma unroll
            for (int q = 0; q < 4; q++) acc[i][j][q] = 0.f;

    auto load_stage = [&](int k0, int buf) {
        #pragma unroll
        for (int i = 0; i < 2; i++) {
            int u = t + 256 * i;
            int r = u >> 2, s = u & 3;
            cp16(&As[buf][r * 40 + s * 8],
                 g_xrh + (size_t)(r0 + r) * C_ + k0 + s * 8, r0 + r < R);
        }
        {
            int r = t >> 2, s = t & 3;
            cp16(&Bs[buf][r * 40 + s * 8],
                 W + (size_t)(c0 + r) * C_ + k0 + s * 8, true);
        }
    };

    load_stage(0, 0);
    cp_commit();

    for (int it = 0; it < 8; it++) {
        int buf = it & 1;
        if (it + 1 < 8) load_stage((it + 1) * 32, buf ^ 1);
        cp_commit();
        cp_wait<1>();
        __syncthreads();
        #pragma unroll
        for (int ks = 0; ks < 2; ks++) {
            unsigned a[2][4];
            #pragma unroll
            for (int mf = 0; mf < 2; mf++) {
                unsigned addr = sm_u32(&As[buf][(wm * 32 + mf * 16 + (lane & 15)) * 40
                                       + ks * 16 + ((lane >> 4) << 3)]);
                ldsm4(addr, a[mf][0], a[mf][1], a[mf][2], a[mf][3]);
            }
            unsigned bf[2][4];
            #pragma unroll
            for (int p = 0; p < 2; p++) {
                unsigned addr = sm_u32(&Bs[buf][(wn * 32 + p * 16 + (lane & 15)) * 40
                                       + ks * 16 + ((lane >> 4) << 3)]);
                ldsm4(addr, bf[p][0], bf[p][1], bf[p][2], bf[p][3]);
            }
            #pragma unroll
            for (int mf = 0; mf < 2; mf++)
                #pragma unroll
                for (int p = 0; p < 2; p++) {
                    mma16816(acc[mf][2 * p],     a[mf][0], a[mf][1], a[mf][2], a[mf][3], bf[p][0], bf[p][2]);
                    mma16816(acc[mf][2 * p + 1], a[mf][0], a[mf][1], a[mf][2], a[mf][3], bf[p][1], bf[p][3]);
                }
        }
        __syncthreads();
    }
    #pragma unroll
    for (int mf = 0; mf < 2; mf++) {
        #pragma unroll
        for (int hh = 0; hh < 2; hh++) {
            int r = r0 + wm * 32 + mf * 16 + (lane >> 2) + hh * 8;
            if (r >= R) continue;
            #pragma unroll
            for (int nf = 0; nf < 4; nf++) {
                int c = c0 + wn * 32 + nf * 8 + (lane & 3) * 2;
                float v0 = acc[mf][nf][hh * 2 + 0] + bias[c];
                float v1 = acc[mf][nf][hh * 2 + 1] + bias[c + 1];
                if (mode == 1) {
                    *(__half2*)(g_kh + (size_t)r * C_ + c) = __floats2half2_rn(v0, v1);
                } else {
                    int bb = r / M_, m = r - bb * M_;
                    g_vt[((size_t)bb * C_ + c)     * VST + m] = __float2half(v0);
                    g_vt[((size_t)bb * C_ + c + 1) * VST + m] = __float2half(v1);
                }
            }
        }
    }
}

// ===========================================================================
// Kernel 4: flash attention — QK fp16-acc MMA; l row-sums via HADD2 tree
// (off the tensor pipe: deletes 16 of 144 MMAs per warp-tile).
// ===========================================================================
#define NT2 20
#define NEGBIG2 0xDF00DF00u   // half2(-448, -448): ex2 -> 0
__global__ __launch_bounds__(128, 4) void k_attn(float* __restrict__ out) {
    __shared__ __half Ks[2][128 * 40];   // 10240 B each
    __shared__ __half Vt[2][32 * 136];   //  8704 B each

    const int b = blockIdx.z, h = blockIdx.y;
    const int t = threadIdx.x, lane = t & 31, w = t >> 5;
    const int n0 = blockIdx.x * 128;

    // stage Q (128 x 32) through Ks[0], then hold fragments in registers
    #pragma unroll
    for (int i = 0; i < 4; i++) {
        int u = t + 128 * i;
        int r = u >> 2, s = u & 3;
        cp16(&Ks[0][r * 40 + s * 8],
             g_qh + ((size_t)(b * N_ + n0 + r)) * C_ + h * 32 + s * 8, n0 + r < N_);
    }
    cp_commit();
    cp_wait<0>();
    __syncthreads();
    unsigned qa[2][2][4];   // [mf][ks]
    #pragma unroll
    for (int mf = 0; mf < 2; mf++)
        #pragma unroll
        for (int ks = 0; ks < 2; ks++) {
            unsigned addr = sm_u32(&Ks[0][(w * 32 + mf * 16 + (lane & 15)) * 40
                                   + ks * 16 + ((lane >> 4) << 3)]);
            ldsm4(addr, qa[mf][ks][0], qa[mf][ks][1], qa[mf][ks][2], qa[mf][ks][3]);
        }
    __syncthreads();   // all warps done with Q before Ks[0] is recycled

    const __half* Kg = g_kh + ((size_t)b * M_) * C_ + h * 32;
    const __half* Vg = g_vt + ((size_t)(b * C_ + h * 32)) * VST;
    auto load_kv = [&](int tile, int buf) {
        int m0 = tile * 128;
        #pragma unroll
        for (int i = 0; i < 4; i++) {
            int u = t + 128 * i;
            int r = u >> 2, s = u & 3;
            cp16(&Ks[buf][r * 40 + s * 8], Kg + (size_t)(m0 + r) * C_ + s * 8, m0 + r < M_);
        }
        #pragma unroll
        for (int i = 0; i < 4; i++) {
            int u = t + 128 * i;
            int r = u >> 4, s = u & 15;
            cp16(&Vt[buf][r * 136 + s * 8], Vg + (size_t)r * VST + m0 + s * 8, true);
        }
    };

    load_kv(0, 0);
    cp_commit();

    float lrow[2][2];   // [mf][row-fragment]: fp32 running row sums
    #pragma unroll
    for (int mf = 0; mf < 2; mf++) { lrow[mf][0] = 0.f; lrow[mf][1] = 0.f; }
    float oacc[2][4][4];
    #pragma unroll
    for (int mf = 0; mf < 2; mf++)
        #pragma unroll
        for (int i = 0; i < 4; i++)
            #pragma unroll
            for (int j = 0; j < 4; j++) oacc[mf][i][j] = 0.f;

    const unsigned lane_off = (lane & 15) * 40 + ((lane >> 4) << 3);

    for (int tile = 0; tile < NT2; tile++) {
        const int buf = tile & 1;
        if (tile + 1 < NT2) load_kv(tile + 1, buf ^ 1);
        cp_commit();
        cp_wait<1>();
        __syncthreads();

        #pragma unroll
        for (int half = 0; half < 2; half++) {
            unsigned ph[2][8][2];
            // QK with fp16 accumulation: C fragment {c01, c23} is the packed P
            #pragma unroll
            for (int p = 0; p < 4; p++) {
                unsigned ch[2][2][2];   // [mf][f][reg]
                #pragma unroll
                for (int mf = 0; mf < 2; mf++)
                    #pragma unroll
                    for (int f = 0; f < 2; f++) {
                        ch[mf][f][0] = 0u; ch[mf][f][1] = 0u;
                    }
                #pragma unroll
                for (int ks = 0; ks < 2; ks++) {
                    unsigned bb0, bb1, bb2, bb3;
                    unsigned addr = sm_u32(&Ks[buf][(half * 64 + p * 16) * 40 + ks * 16]) + lane_off * 2;
                    ldsm4(addr, bb0, bb1, bb2, bb3);
                    #pragma unroll
                    for (int mf = 0; mf < 2; mf++) {
                        mma16816h(ch[mf][0][0], ch[mf][0][1], qa[mf][ks][0], qa[mf][ks][1],
                                  qa[mf][ks][2], qa[mf][ks][3], bb0, bb2);
                        mma16816h(ch[mf][1][0], ch[mf][1][1], qa[mf][ks][0], qa[mf][ks][1],
                                  qa[mf][ks][2], qa[mf][ks][3], bb1, bb3);
                    }
                }
                // mask tail keys (M_ even => key pairs never straddle the edge)
                if (tile == NT2 - 1) {
                    #pragma unroll
                    for (int f = 0; f < 2; f++) {
                        int key = tile * 128 + half * 64 + (p * 2 + f) * 8 + (lane & 3) * 2;
                        if (key >= M_) {
                            #pragma unroll
                            for (int mf = 0; mf < 2; mf++) {
                                ch[mf][f][0] = NEGBIG2; ch[mf][f][1] = NEGBIG2;
                            }
                        }
                    }
                }
                #pragma unroll
                for (int mf = 0; mf < 2; mf++)
                    #pragma unroll
                    for (int f = 0; f < 2; f++) {
                        ph[mf][p * 2 + f][0] = h2ex2(ch[mf][f][0]);
                        ph[mf][p * 2 + f][1] = h2ex2(ch[mf][f][1]);
                    }
            }
            // l row-sums via HADD2 tree (fma pipe; off the tensor pipe)
            #pragma unroll
            for (int mf = 0; mf < 2; mf++) {
                #pragma unroll
                for (int j = 0; j < 2; j++) {
                    unsigned s0 = hadd2u(hadd2u(ph[mf][0][j], ph[mf][1][j]),
                                         hadd2u(ph[mf][2][j], ph[mf][3][j]));
                    unsigned s1 = hadd2u(hadd2u(ph[mf][4][j], ph[mf][5][j]),
                                         hadd2u(ph[mf][6][j], ph[mf][7][j]));
                    unsigned s  = hadd2u(s0, s1);
                    float2 f2 = __half22float2(*reinterpret_cast<__half2*>(&s));
                    lrow[mf][j] += f2.x + f2.y;
                }
            }
            // O += P V  (fp32 accumulate on the tensor pipe)
            #pragma unroll
            for (int kk = 0; kk < 4; kk++) {
                #pragma unroll
                for (int p = 0; p < 2; p++) {
                    unsigned bb0, bb1, bb2, bb3;
                    unsigned addr = sm_u32(&Vt[buf][(p * 16 + (lane & 15)) * 136
                                           + (half * 4 + kk) * 16 + ((lane >> 4) << 3)]);
                    ldsm4(addr, bb0, bb1, bb2, bb3);
                    #pragma unroll
                    for (int mf = 0; mf < 2; mf++) {
                        mma16816(oacc[mf][2 * p],     ph[mf][2 * kk][0], ph[mf][2 * kk][1],
                                 ph[mf][2 * kk + 1][0], ph[mf][2 * kk + 1][1], bb0, bb2);
                        mma16816(oacc[mf][2 * p + 1], ph[mf][2 * kk][0], ph[mf][2 * kk][1],
                                 ph[mf][2 * kk + 1][0], ph[mf][2 * kk + 1][1], bb1, bb3);
                    }
                }
            }
        }
        __syncthreads();
    }

    // lrow holds per-thread partials over this thread's (lane&3) column slice;
    // reduce across the 4 lanes of each row quad.
    #pragma unroll
    for (int mf = 0; mf < 2; mf++)
        #pragma unroll
        for (int j = 0; j < 2; j++) {
            lrow[mf][j] += __shfl_xor_sync(0xffffffffu, lrow[mf][j], 1);
            lrow[mf][j] += __shfl_xor_sync(0xffffffffu, lrow[mf][j], 2);
        }

    #pragma unroll
    for (int mf = 0; mf < 2; mf++) {
        float inv0 = 1.f / lrow[mf][0];
        float inv1 = 1.f / lrow[mf][1];
        int r = n0 + w * 32 + mf * 16 + (lane >> 2);
        #pragma unroll
        for (int nf = 0; nf < 4; nf++) {
            int d = h * 32 + nf * 8 + (lane & 3) * 2;
            if (r < N_) {
                *(float2*)(out + ((size_t)(b * N_ + r)) * C_ + d) =
                    make_float2(oacc[mf][nf][0] * inv0, oacc[mf][nf][1] * inv0);
            }
            if (r + 8 < N_) {
                *(float2*)(out + ((size_t)(b * N_ + r + 8)) * C_ + d) =
                    make_float2(oacc[mf][nf][2] * inv1, oacc[mf][nf][3] * inv1);
            }
        }
    }
}

// ---------------------------------------------------------------------------
extern "C" void kernel_launch(void* const* d_in, const int* in_sizes, int n_in,
                              void* d_out, int out_size) {
    (void)in_sizes; (void)n_in; (void)out_size;
    const float* x     = (const float*)d_in[0];
    const float* Wq    = (const float*)d_in[1];
    const float* bq    = (const float*)d_in[2];
    const float* Wk    = (const float*)d_in[3];
    const float* bk    = (const float*)d_in[4];
    const float* Wv    = (const float*)d_in[5];
    const float* bv    = (const float*)d_in[6];
    const float* Wc    = (const float*)d_in[7];
    const float* gamma = (const float*)d_in[9];
    const float* beta  = (const float*)d_in[10];
    float* out = (float*)d_out;

    static bool attr_done = false;
    if (!attr_done) {
        cudaFuncSetAttribute(k_red_projQ, cudaFuncAttributeMaxDynamicSharedMemorySize,
                             RED_SMEM);
        attr_done = true;
    }

    k_pre<<<TRX_CTAS + 384, 256>>>(x, Wq, Wk, Wv);
    k_red_projQ<<<RED_CTAS + PQ_CTAS, 256, RED_SMEM>>>(Wc, gamma, beta, x, bq);
    k_projKV<<<2 * KV_CTAS, 256>>>(bk, bv);
    dim3 ga((N_ + 127) / 128, H_, B_);
    k_attn<<<ga, 128>>>(out);
}

// round 14
// speedup vs baseline: 1.2128x; 1.1780x over previous
#include <cuda_runtime.h>
#include <cuda_fp16.h>

#define B_  2
#define N_  5000
#define C_  256
#define H_  8
#define M_  2500
#define DK_ 32
#define VST 2560   // padded M stride for g_vt, pad stays 0
#define KSPLIT 2496  // K split boundary (multiple of 32; keeps 16B alignment)

// ---------------- scratch (device globals; zero-initialized) ---------------
__device__ __half g_xth[B_*C_*N_];    // x^T fp16 (B,C,N)
__device__ __half g_Wqh[C_*C_];
__device__ __half g_Wkh[C_*C_];
__device__ __half g_Wvh[C_*C_];
__device__ float  g_xr2[2][B_*M_*C_]; // split-K partial sums (fp32)
__device__ __half g_xrh[B_*M_*C_];    // LN output fp16
__device__ __half g_qh [B_*N_*C_];    // Q (pre-scaled by 1/sqrt(32)*log2e)
__device__ __half g_kh [B_*M_*C_];
__device__ __half g_vt [B_*C_*VST];   // V^T (B,C,Mpad)

// ---------------- helpers ---------------------------------------------------
__device__ __forceinline__ unsigned sm_u32(const void* p) {
    return (unsigned)__cvta_generic_to_shared(p);
}
__device__ __forceinline__ void ldsm4(unsigned addr, unsigned& r0, unsigned& r1,
                                      unsigned& r2, unsigned& r3) {
    asm volatile("ldmatrix.sync.aligned.m8n8.x4.shared.b16 {%0,%1,%2,%3}, [%4];"
                 : "=r"(r0), "=r"(r1), "=r"(r2), "=r"(r3) : "r"(addr));
}
__device__ __forceinline__ void mma16816(float* c, unsigned a0, unsigned a1,
                                         unsigned a2, unsigned a3,
                                         unsigned b0, unsigned b1) {
    asm volatile("mma.sync.aligned.m16n8k16.row.col.f32.f16.f16.f32 "
                 "{%0,%1,%2,%3}, {%4,%5,%6,%7}, {%8,%9}, {%0,%1,%2,%3};"
                 : "+f"(c[0]), "+f"(c[1]), "+f"(c[2]), "+f"(c[3])
                 : "r"(a0), "r"(a1), "r"(a2), "r"(a3), "r"(b0), "r"(b1));
}
// fp16-accumulate variant: C/D are 2 regs of packed half2
__device__ __forceinline__ void mma16816h(unsigned& c0, unsigned& c1,
                                          unsigned a0, unsigned a1,
                                          unsigned a2, unsigned a3,
                                          unsigned b0, unsigned b1) {
    asm volatile("mma.sync.aligned.m16n8k16.row.col.f16.f16.f16.f16 "
                 "{%0,%1}, {%2,%3,%4,%5}, {%6,%7}, {%0,%1};"
                 : "+r"(c0), "+r"(c1)
                 : "r"(a0), "r"(a1), "r"(a2), "r"(a3), "r"(b0), "r"(b1));
}
__device__ __forceinline__ unsigned pack2(float a, float b) {
    __half2 h = __floats2half2_rn(a, b);
    return *reinterpret_cast<unsigned*>(&h);
}
__device__ __forceinline__ unsigned h2ex2(unsigned x) {
    unsigned y;
    asm("ex2.approx.f16x2 %0, %1;" : "=r"(y) : "r"(x));
    return y;
}
__device__ __forceinline__ void cp16(void* dst_smem, const void* src, bool pred) {
    unsigned d = sm_u32(dst_smem);
    int sz = pred ? 16 : 0;
    asm volatile("cp.async.cg.shared.global [%0], [%1], 16, %2;"
                 :: "r"(d), "l"(src), "r"(sz));
}
__device__ __forceinline__ void cp_commit() {
    asm volatile("cp.async.commit_group;");
}
template <int NN>
__device__ __forceinline__ void cp_wait() {
    asm volatile("cp.async.wait_group %0;" :: "n"(NN));
}

// ===========================================================================
// Kernel 1: fused x-transpose + W converts
// ===========================================================================
#define TRX_CTAS 2512   // 8 * 157 * 2
__global__ __launch_bounds__(256) void k_pre(const float* __restrict__ x,
                                             const float* __restrict__ Wq,
                                             const float* __restrict__ Wk,
                                             const float* __restrict__ Wv) {
    __shared__ float tile[32][33];
    const int id = blockIdx.x;
    if (id < TRX_CTAS) {
        int c_idx = id & 7;
        int n_idx = (id >> 3) % 157;
        int b     = id / (8 * 157);
        int c0 = c_idx * 32, n0 = n_idx * 32;
        int tx = threadIdx.x & 31, ty = threadIdx.x >> 5;
        #pragma unroll
        for (int i = 0; i < 4; i++) {
            int n = n0 + ty + i * 8;
            tile[ty + i * 8][tx] = (n < N_) ? x[((size_t)b * N_ + n) * C_ + c0 + tx] : 0.f;
        }
        __syncthreads();
        #pragma unroll
        for (int i = 0; i < 4; i++) {
            int n = n0 + tx;
            int c = c0 + ty + i * 8;
            if (n < N_) g_xth[((size_t)b * C_ + c) * N_ + n] = __float2half(tile[tx][ty + i * 8]);
        }
    } else {
        int id2 = id - TRX_CTAS;
        int sel = id2 >> 7;
        int blk = id2 & 127;
        const float* in = (sel == 0) ? Wq : ((sel == 1) ? Wk : Wv);
        __half* out = (sel == 0) ? g_Wqh : ((sel == 1) ? g_Wkh : g_Wvh);
        int i = (blk * 256 + threadIdx.x) * 2;
        float2 v = *(const float2*)(in + i);
        *(__half2*)(out + i) = __floats2half2_rn(v.x, v.y);
    }
}

// ===========================================================================
// Kernel 2: merged [split-K reduce-GEMM] + Q-projection
//   reduce: 64-row x 256-col tiles, K split in two halves -> 160 CTAs,
//   partial fp32 sums to g_xr2[kh]; LN done by k_ln afterwards.
// ===========================================================================
#define RED_CTAS 160     // 2 (kh) * 2 (b) * 40 (m-blocks)
#define PQ_CTAS  316
#define RED_SMEM 51200

__device__ void reduce_part(char* dsm, const float* __restrict__ Wc, int id) {
    __half* As0 = (__half*)dsm;                  // 2 stages x 64*40
    __half* Bs0 = (__half*)(dsm + 10240);        // 2 stages x 256*40

    const int b  = id & 1;
    const int mb = (id >> 1) % 40;
    const int kh = id / 80;
    const int m0 = mb * 64;
    const int kbase = kh ? KSPLIT : 0;
    const int kend  = kh ? N_ : KSPLIT;
    const int ITERS = kh ? 79 : 78;              // ceil((kend-kbase)/32)
    const int t = threadIdx.x, lane = t & 31, w = t >> 5;
    const int wm = w >> 2, wn = w & 3;
    const __half* Bg = g_xth + (size_t)b * C_ * N_;
    float* outp = g_xr2[kh] + (size_t)b * M_ * C_;

    const int lr = t >> 2, ls = t & 3;

    float acc[2][8][4];
    #pragma unroll
    for (int i = 0; i < 2; i++)
        #pragma unroll
        for (int j = 0; j < 8; j++)
            #pragma unroll
            for (int q = 0; q < 4; q++) acc[i][j][q] = 0.f;

    float4 ar[2];
    auto ldgA = [&](int k0) {
        int gm = m0 + lr, gk = kbase + k0 + ls * 8;
        if (gm < M_ && gk + 8 <= kend) {
            const float* p = Wc + (size_t)gm * N_ + gk;
            ar[0] = *(const float4*)(p);
            ar[1] = *(const float4*)(p + 4);
        } else {
            ar[0] = make_float4(0.f, 0.f, 0.f, 0.f);
            ar[1] = make_float4(0.f, 0.f, 0.f, 0.f);
        }
    };
    auto stsA = [&](int buf) {
        uint4 v;
        v.x = pack2(ar[0].x, ar[0].y); v.y = pack2(ar[0].z, ar[0].w);
        v.z = pack2(ar[1].x, ar[1].y); v.w = pack2(ar[1].z, ar[1].w);
        *(uint4*)(As0 + buf * 2560 + lr * 40 + ls * 8) = v;
    };
    auto cpB = [&](int k0, int buf) {
        #pragma unroll
        for (int i = 0; i < 4; i++) {
            int u = t + 256 * i;
            int r = u >> 2, s = u & 3;
            int gk = kbase + k0 + s * 8;
            cp16(Bs0 + buf * 10240 + r * 40 + s * 8,
                 Bg + (size_t)r * N_ + gk, gk + 8 <= kend);
        }
    };

    ldgA(0);
    stsA(0);
    cpB(0, 0);
    cp_commit();

    for (int tt = 0; tt < ITERS; tt++) {
        int buf = tt & 1;
        if (tt + 1 < ITERS) {
            ldgA((tt + 1) * 32);
            cpB((tt + 1) * 32, buf ^ 1);
        }
        cp_commit();
        cp_wait<1>();
        __syncthreads();

        #pragma unroll
        for (int ks = 0; ks < 2; ks++) {
            unsigned a[2][4];
            #pragma unroll
            for (int mf = 0; mf < 2; mf++) {
                unsigned addr = sm_u32(As0 + buf * 2560 + (wm * 32 + mf * 16 + (lane & 15)) * 40
                                       + ks * 16 + ((lane >> 4) << 3));
                ldsm4(addr, a[mf][0], a[mf][1], a[mf][2], a[mf][3]);
            }
            #pragma unroll
            for (int p = 0; p < 4; p++) {
                unsigned b0, b1, b2, b3;
                unsigned addr = sm_u32(Bs0 + buf * 10240 + (wn * 64 + p * 16 + (lane & 15)) * 40
                                       + ks * 16 + ((lane >> 4) << 3));
                ldsm4(addr, b0, b1, b2, b3);
                #pragma unroll
                for (int mf = 0; mf < 2; mf++) {
                    mma16816(acc[mf][2 * p],     a[mf][0], a[mf][1], a[mf][2], a[mf][3], b0, b2);
                    mma16816(acc[mf][2 * p + 1], a[mf][0], a[mf][1], a[mf][2], a[mf][3], b1, b3);
                }
            }
        }
        if (tt + 1 < ITERS) stsA(buf ^ 1);
        __syncthreads();
    }

    // store fp32 partials (no bias: bc cancels in the downstream LayerNorm)
    #pragma unroll
    for (int mf = 0; mf < 2; mf++) {
        #pragma unroll
        for (int hh = 0; hh < 2; hh++) {
            int r = m0 + wm * 32 + mf * 16 + (lane >> 2) + hh * 8;
            if (r >= M_) continue;
            #pragma unroll
            for (int nf = 0; nf < 8; nf++) {
                int c = wn * 64 + nf * 8 + (lane & 3) * 2;
                *(float2*)(outp + (size_t)r * C_ + c) =
                    make_float2(acc[mf][nf][hh * 2 + 0], acc[mf][nf][hh * 2 + 1]);
            }
        }
    }
}

__device__ void projQ_part(char* dsm, const float* __restrict__ x,
                           const float* __restrict__ bq, int id) {
    __half* As = (__half*)dsm;
    __half* Bs = (__half*)(dsm + 10240);

    const int r0 = (id >> 2) * 128;
    const int c0 = (id & 3) * 64;
    const int t = threadIdx.x, lane = t & 31, w = t >> 5;
    const int wm = w >> 1, wn = w & 1;
    const int R = B_ * N_;
    const float qscale = 0.17677669529663687f * 1.4426950408889634f;

    float acc[2][4][4];
    #pragma unroll
    for (int i = 0; i < 2; i++)
        #pragma unroll
        for (int j = 0; j < 4; j++)
            #pragma unroll
            for (int q = 0; q < 4; q++) acc[i][j][q] = 0.f;

    for (int k0 = 0; k0 < C_; k0 += 32) {
        #pragma unroll
        for (int i = 0; i < 2; i++) {
            int u = t + 256 * i;
            int r = u >> 2, s = u & 3;
            int gr = r0 + r;
            uint4 v = make_uint4(0, 0, 0, 0);
            if (gr < R) {
                const float* p = x + (size_t)gr * C_ + k0 + s * 8;
                float4 f0 = *(const float4*)(p);
                float4 f1 = *(const float4*)(p + 4);
                v.x = pack2(f0.x, f0.y); v.y = pack2(f0.z, f0.w);
                v.z = pack2(f1.x, f1.y); v.w = pack2(f1.z, f1.w);
            }
            *(uint4*)(As + r * 40 + s * 8) = v;
        }
        {
            int r = t >> 2, s = t & 3;
            uint4 v = *(const uint4*)(g_Wqh + (size_t)(c0 + r) * C_ + k0 + s * 8);
            *(uint4*)(Bs + r * 40 + s * 8) = v;
        }
        __syncthreads();
        #pragma unroll
        for (int ks = 0; ks < 2; ks++) {
            unsigned a[2][4];
            #pragma unroll
            for (int mf = 0; mf < 2; mf++) {
                unsigned addr = sm_u32(As + (wm * 32 + mf * 16 + (lane & 15)) * 40
                                       + ks * 16 + ((lane >> 4) << 3));
                ldsm4(addr, a[mf][0], a[mf][1], a[mf][2], a[mf][3]);
            }
            unsigned bf[2][4];
            #pragma unroll
            for (int p = 0; p < 2; p++) {
                unsigned addr = sm_u32(Bs + (wn * 32 + p * 16 + (lane & 15)) * 40
                                       + ks * 16 + ((lane >> 4) << 3));
                ldsm4(addr, bf[p][0], bf[p][1], bf[p][2], bf[p][3]);
            }
            #pragma unroll
            for (int mf = 0; mf < 2; mf++)
                #pragma unroll
                for (int p = 0; p < 2; p++) {
                    mma16816(acc[mf][2 * p],     a[mf][0], a[mf][1], a[mf][2], a[mf][3], bf[p][0], bf[p][2]);
                    mma16816(acc[mf][2 * p + 1], a[mf][0], a[mf][1], a[mf][2], a[mf][3], bf[p][1], bf[p][3]);
                }
        }
        __syncthreads();
    }
    #pragma unroll
    for (int mf = 0; mf < 2; mf++) {
        #pragma unroll
        for (int hh = 0; hh < 2; hh++) {
            int r = r0 + wm * 32 + mf * 16 + (lane >> 2) + hh * 8;
            if (r >= R) continue;
            #pragma unroll
            for (int nf = 0; nf < 4; nf++) {
                int c = c0 + wn * 32 + nf * 8 + (lane & 3) * 2;
                float v0 = (acc[mf][nf][hh * 2 + 0] + bq[c])     * qscale;
                float v1 = (acc[mf][nf][hh * 2 + 1] + bq[c + 1]) * qscale;
                *(__half2*)(g_qh + (size_t)r * C_ + c) = __floats2half2_rn(v0, v1);
            }
        }
    }
}

__global__ __launch_bounds__(256) void k_red_projQ(const float* __restrict__ Wc,
                                                   const float* __restrict__ x,
                                                   const float* __restrict__ bq) {
    extern __shared__ __align__(16) char dsm[];
    if (blockIdx.x < RED_CTAS) reduce_part(dsm, Wc, blockIdx.x);
    else                       projQ_part(dsm, x, bq, blockIdx.x - RED_CTAS);
}

// ===========================================================================
// Kernel 2b: sum split-K partials + LayerNorm -> g_xrh (warp per row)
// ===========================================================================
__global__ __launch_bounds__(256) void k_ln(const float* __restrict__ gamma,
                                            const float* __restrict__ beta) {
    const int row  = blockIdx.x * 8 + (threadIdx.x >> 5);
    const int lane = threadIdx.x & 31;
    const float* X0 = g_xr2[0] + (size_t)row * C_ + lane * 8;
    const float* X1 = g_xr2[1] + (size_t)row * C_ + lane * 8;
    float4 a0 = *(const float4*)(X0),     a1 = *(const float4*)(X0 + 4);
    float4 b0v = *(const float4*)(X1),    b1v = *(const float4*)(X1 + 4);
    float4 a  = make_float4(a0.x + b0v.x, a0.y + b0v.y, a0.z + b0v.z, a0.w + b0v.w);
    float4 bv = make_float4(a1.x + b1v.x, a1.y + b1v.y, a1.z + b1v.z, a1.w + b1v.w);

    float s  = a.x + a.y + a.z + a.w + bv.x + bv.y + bv.z + bv.w;
    float s2 = a.x*a.x + a.y*a.y + a.z*a.z + a.w*a.w
             + bv.x*bv.x + bv.y*bv.y + bv.z*bv.z + bv.w*bv.w;
    #pragma unroll
    for (int o = 16; o; o >>= 1) {
        s  += __shfl_xor_sync(0xffffffffu, s,  o);
        s2 += __shfl_xor_sync(0xffffffffu, s2, o);
    }
    float mu  = s * (1.f / 256.f);
    float var = s2 * (1.f / 256.f) - mu * mu;
    float rs  = rsqrtf(var + 1e-5f);

    const float* gp = gamma + lane * 8;
    const float* bp = beta  + lane * 8;
    float4 g0 = *(const float4*)(gp), g1 = *(const float4*)(gp + 4);
    float4 e0 = *(const float4*)(bp), e1 = *(const float4*)(bp + 4);

    uint4 outv;
    outv.x = pack2(g0.x*(a.x-mu)*rs + e0.x,  g0.y*(a.y-mu)*rs + e0.y);
    outv.y = pack2(g0.z*(a.z-mu)*rs + e0.z,  g0.w*(a.w-mu)*rs + e0.w);
    outv.z = pack2(g1.x*(bv.x-mu)*rs + e1.x, g1.y*(bv.y-mu)*rs + e1.y);
    outv.w = pack2(g1.z*(bv.z-mu)*rs + e1.z, g1.w*(bv.w-mu)*rs + e1.w);
    *(uint4*)(g_xrh + (size_t)row * C_ + lane * 8) = outv;
}

// ===========================================================================
// Kernel 3: K and V projections, 2-stage cp.async pipeline
// ===========================================================================
#define KV_CTAS 160
__global__ __launch_bounds__(256) void k_projKV(const float* __restrict__ bk,
                                                const float* __restrict__ bv) {
    __shared__ __align__(16) __half As[2][128 * 40];
    __shared__ __align__(16) __half Bs[2][64 * 40];

    const int id = blockIdx.x;
    const int mode = (id < KV_CTAS) ? 1 : 2;
    const int rid = (mode == 1) ? id : id - KV_CTAS;
    const int r0 = (rid >> 2) * 128;
    const int c0 = (rid & 3) * 64;
    const __half* W   = (mode == 1) ? g_Wkh : g_Wvh;
    const float* bias = (mode == 1) ? bk : bv;
    const int R = B_ * M_;

    const int t = threadIdx.x, lane = t & 31, w = t >> 5;
    const int wm = w >> 1, wn = w & 1;

    float acc[2][4][4];
    #pragma unroll
    for (int i = 0; i < 2; i++)
        #pragma unroll
        for (int j = 0; j < 4; j++)
            #pragma unroll
            for (int q = 0; q < 4; q++) acc[i][j][q] = 0.f;

    auto load_stage = [&](int k0, int buf) {
        #pragma unroll
        for (int i = 0; i < 2; i++) {
            int u = t + 256 * i;
            int r = u >> 2, s = u & 3;
            cp16(&As[buf][r * 40 + s * 8],
                 g_xrh + (size_t)(r0 + r) * C_ + k0 + s * 8, r0 + r < R);
        }
        {
            int r = t >> 2, s = t & 3;
            cp16(&Bs[buf][r * 40 + s * 8],
                 W + (size_t)(c0 + r) * C_ + k0 + s * 8, true);
        }
    };

    load_stage(0, 0);
    cp_commit();

    for (int it = 0; it < 8; it++) {
        int buf = it & 1;
        if (it + 1 < 8) load_stage((it + 1) * 32, buf ^ 1);
        cp_commit();
        cp_wait<1>();
        __syncthreads();
        #pragma unroll
        for (int ks = 0; ks < 2; ks++) {
            unsigned a[2][4];
            #pragma unroll
            for (int mf = 0; mf < 2; mf++) {
                unsigned addr = sm_u32(&As[buf][(wm * 32 + mf * 16 + (lane & 15)) * 40
                                       + ks * 16 + ((lane >> 4) << 3)]);
                ldsm4(addr, a[mf][0], a[mf][1], a[mf][2], a[mf][3]);
            }
            unsigned bf[2][4];
            #pragma unroll
            for (int p = 0; p < 2; p++) {
                unsigned addr = sm_u32(&Bs[buf][(wn * 32 + p * 16 + (lane & 15)) * 40
                                       + ks * 16 + ((lane >> 4) << 3)]);
                ldsm4(addr, bf[p][0], bf[p][1], bf[p][2], bf[p][3]);
            }
            #pragma unroll
            for (int mf = 0; mf < 2; mf++)
                #pragma unroll
                for (int p = 0; p < 2; p++) {
                    mma16816(acc[mf][2 * p],     a[mf][0], a[mf][1], a[mf][2], a[mf][3], bf[p][0], bf[p][2]);
                    mma16816(acc[mf][2 * p + 1], a[mf][0], a[mf][1], a[mf][2], a[mf][3], bf[p][1], bf[p][3]);
                }
        }
        __syncthreads();
    }
    #pragma unroll
    for (int mf = 0; mf < 2; mf++) {
        #pragma unroll
        for (int hh = 0; hh < 2; hh++) {
            int r = r0 + wm * 32 + mf * 16 + (lane >> 2) + hh * 8;
            if (r >= R) continue;
            #pragma unroll
            for (int nf = 0; nf < 4; nf++) {
                int c = c0 + wn * 32 + nf * 8 + (lane & 3) * 2;
                float v0 = acc[mf][nf][hh * 2 + 0] + bias[c];
                float v1 = acc[mf][nf][hh * 2 + 1] + bias[c + 1];
                if (mode == 1) {
                    *(__half2*)(g_kh + (size_t)r * C_ + c) = __floats2half2_rn(v0, v1);
                } else {
                    int bb = r / M_, m = r - bb * M_;
                    g_vt[((size_t)bb * C_ + c)     * VST + m] = __float2half(v0);
                    g_vt[((size_t)bb * C_ + c + 1) * VST + m] = __float2half(v1);
                }
            }
        }
    }
}

// ===========================================================================
// Kernel 4: flash attention — R11 configuration (best known): QK fp16-acc,
// ex2 in place, l via ones-MMA on tensor pipe, PV fp32-acc.
// ===========================================================================
#define NT2 20
#define ONES2 0x3C003C00u
#define NEGBIG2 0xDF00DF00u   // half2(-448, -448): ex2 -> 0
__global__ __launch_bounds__(128, 4) void k_attn(float* __restrict__ out) {
    __shared__ __half Ks[2][128 * 40];   // 10240 B each
    __shared__ __half Vt[2][32 * 136];   //  8704 B each

    const int b = blockIdx.z, h = blockIdx.y;
    const int t = threadIdx.x, lane = t & 31, w = t >> 5;
    const int n0 = blockIdx.x * 128;

    // stage Q (128 x 32) through Ks[0], then hold fragments in registers
    #pragma unroll
    for (int i = 0; i < 4; i++) {
        int u = t + 128 * i;
        int r = u >> 2, s = u & 3;
        cp16(&Ks[0][r * 40 + s * 8],
             g_qh + ((size_t)(b * N_ + n0 + r)) * C_ + h * 32 + s * 8, n0 + r < N_);
    }
    cp_commit();
    cp_wait<0>();
    __syncthreads();
    unsigned qa[2][2][4];   // [mf][ks]
    #pragma unroll
    for (int mf = 0; mf < 2; mf++)
        #pragma unroll
        for (int ks = 0; ks < 2; ks++) {
            unsigned addr = sm_u32(&Ks[0][(w * 32 + mf * 16 + (lane & 15)) * 40
                                   + ks * 16 + ((lane >> 4) << 3)]);
            ldsm4(addr, qa[mf][ks][0], qa[mf][ks][1], qa[mf][ks][2], qa[mf][ks][3]);
        }
    __syncthreads();   // all warps done with Q before Ks[0] is recycled

    const __half* Kg = g_kh + ((size_t)b * M_) * C_ + h * 32;
    const __half* Vg = g_vt + ((size_t)(b * C_ + h * 32)) * VST;
    auto load_kv = [&](int tile, int buf) {
        int m0 = tile * 128;
        #pragma unroll
        for (int i = 0; i < 4; i++) {
            int u = t + 128 * i;
            int r = u >> 2, s = u & 3;
            cp16(&Ks[buf][r * 40 + s * 8], Kg + (size_t)(m0 + r) * C_ + s * 8, m0 + r < M_);
        }
        #pragma unroll
        for (int i = 0; i < 4; i++) {
            int u = t + 128 * i;
            int r = u >> 4, s = u & 15;
            cp16(&Vt[buf][r * 136 + s * 8], Vg + (size_t)r * VST + m0 + s * 8, true);
        }
    };

    load_kv(0, 0);
    cp_commit();

    float lacc[2][4];
    #pragma unroll
    for (int mf = 0; mf < 2; mf++)
        #pragma unroll
        for (int j = 0; j < 4; j++) lacc[mf][j] = 0.f;
    float oacc[2][4][4];
    #pragma unroll
    for (int mf = 0; mf < 2; mf++)
        #pragma unroll
        for (int i = 0; i < 4; i++)
            #pragma unroll
            for (int j = 0; j < 4; j++) oacc[mf][i][j] = 0.f;

    const unsigned lane_off = (lane & 15) * 40 + ((lane >> 4) << 3);

    for (int tile = 0; tile < NT2; tile++) {
        const int buf = tile & 1;
        if (tile + 1 < NT2) load_kv(tile + 1, buf ^ 1);
        cp_commit();
        cp_wait<1>();
        __syncthreads();

        #pragma unroll
        for (int half = 0; half < 2; half++) {
            unsigned ph[2][8][2];
            // QK with fp16 accumulation: C fragment {c01, c23} is the packed P
            #pragma unroll
            for (int p = 0; p < 4; p++) {
                unsigned ch[2][2][2];   // [mf][f][reg]
                #pragma unroll
                for (int mf = 0; mf < 2; mf++)
                    #pragma unroll
                    for (int f = 0; f < 2; f++) {
                        ch[mf][f][0] = 0u; ch[mf][f][1] = 0u;
                    }
                #pragma unroll
                for (int ks = 0; ks < 2; ks++) {
                    unsigned bb0, bb1, bb2, bb3;
                    unsigned addr = sm_u32(&Ks[buf][(half * 64 + p * 16) * 40 + ks * 16]) + lane_off * 2;
                    ldsm4(addr, bb0, bb1, bb2, bb3);
                    #pragma unroll
                    for (int mf = 0; mf < 2; mf++) {
                        mma16816h(ch[mf][0][0], ch[mf][0][1], qa[mf][ks][0], qa[mf][ks][1],
                                  qa[mf][ks][2], qa[mf][ks][3], bb0, bb2);
                        mma16816h(ch[mf][1][0], ch[mf][1][1], qa[mf][ks][0], qa[mf][ks][1],
                                  qa[mf][ks][2], qa[mf][ks][3], bb1, bb3);
                    }
                }
                // mask tail keys (M_ even => key pairs never straddle the edge)
                if (tile == NT2 - 1) {
                    #pragma unroll
                    for (int f = 0; f < 2; f++) {
                        int key = tile * 128 + half * 64 + (p * 2 + f) * 8 + (lane & 3) * 2;
                        if (key >= M_) {
                            #pragma unroll
                            for (int mf = 0; mf < 2; mf++) {
                                ch[mf][f][0] = NEGBIG2; ch[mf][f][1] = NEGBIG2;
                            }
                        }
                    }
                }
                #pragma unroll
                for (int mf = 0; mf < 2; mf++)
                    #pragma unroll
                    for (int f = 0; f < 2; f++) {
                        ph[mf][p * 2 + f][0] = h2ex2(ch[mf][f][0]);
                        ph[mf][p * 2 + f][1] = h2ex2(ch[mf][f][1]);
                    }
            }
            // O += P V ; l += P @ ones  (fp32 accumulate)
            #pragma unroll
            for (int kk = 0; kk < 4; kk++) {
                #pragma unroll
                for (int mf = 0; mf < 2; mf++)
                    mma16816(lacc[mf], ph[mf][2 * kk][0], ph[mf][2 * kk][1],
                             ph[mf][2 * kk + 1][0], ph[mf][2 * kk + 1][1], ONES2, ONES2);
                #pragma unroll
                for (int p = 0; p < 2; p++) {
                    unsigned bb0, bb1, bb2, bb3;
                    unsigned addr = sm_u32(&Vt[buf][(p * 16 + (lane & 15)) * 136
                                           + (half * 4 + kk) * 16 + ((lane >> 4) << 3)]);
                    ldsm4(addr, bb0, bb1, bb2, bb3);
                    #pragma unroll
                    for (int mf = 0; mf < 2; mf++) {
                        mma16816(oacc[mf][2 * p],     ph[mf][2 * kk][0], ph[mf][2 * kk][1],
                                 ph[mf][2 * kk + 1][0], ph[mf][2 * kk + 1][1], bb0, bb2);
                        mma16816(oacc[mf][2 * p + 1], ph[mf][2 * kk][0], ph[mf][2 * kk][1],
                                 ph[mf][2 * kk + 1][0], ph[mf][2 * kk + 1][1], bb1, bb3);
                    }
                }
            }
        }
        __syncthreads();
    }

    #pragma unroll
    for (int mf = 0; mf < 2; mf++) {
        float inv0 = 1.f / lacc[mf][0];
        float inv1 = 1.f / lacc[mf][2];
        int r = n0 + w * 32 + mf * 16 + (lane >> 2);
        #pragma unroll
        for (int nf = 0; nf < 4; nf++) {
            int d = h * 32 + nf * 8 + (lane & 3) * 2;
            if (r < N_) {
                *(float2*)(out + ((size_t)(b * N_ + r)) * C_ + d) =
                    make_float2(oacc[mf][nf][0] * inv0, oacc[mf][nf][1] * inv0);
            }
            if (r + 8 < N_) {
                *(float2*)(out + ((size_t)(b * N_ + r + 8)) * C_ + d) =
                    make_float2(oacc[mf][nf][2] * inv1, oacc[mf][nf][3] * inv1);
            }
        }
    }
}

// ---------------------------------------------------------------------------
extern "C" void kernel_launch(void* const* d_in, const int* in_sizes, int n_in,
                              void* d_out, int out_size) {
    (void)in_sizes; (void)n_in; (void)out_size;
    const float* x     = (const float*)d_in[0];
    const float* Wq    = (const float*)d_in[1];
    const float* bq    = (const float*)d_in[2];
    const float* Wk    = (const float*)d_in[3];
    const float* bk    = (const float*)d_in[4];
    const float* Wv    = (const float*)d_in[5];
    const float* bv    = (const float*)d_in[6];
    const float* Wc    = (const float*)d_in[7];
    const float* gamma = (const float*)d_in[9];
    const float* beta  = (const float*)d_in[10];
    float* out = (float*)d_out;

    static bool attr_done = false;
    if (!attr_done) {
        cudaFuncSetAttribute(k_red_projQ, cudaFuncAttributeMaxDynamicSharedMemorySize,
                             RED_SMEM);
        attr_done = true;
    }

    k_pre<<<TRX_CTAS + 384, 256>>>(x, Wq, Wk, Wv);
    k_red_projQ<<<RED_CTAS + PQ_CTAS, 256, RED_SMEM>>>(Wc, x, bq);
    k_ln<<<B_ * M_ / 8, 256>>>(gamma, beta);
    k_projKV<<<2 * KV_CTAS, 256>>>(bk, bv);
    dim3 ga((N_ + 127) / 128, H_, B_);
    k_attn<<<ga, 128>>>(out);
}

// round 16
// speedup vs baseline: 1.2232x; 1.0085x over previous
#include <cuda_runtime.h>
#include <cuda_fp16.h>

#define B_  2
#define N_  5000
#define C_  256
#define H_  8
#define M_  2500
#define DK_ 32
#define VST 2560   // padded M stride for g_vt, pad stays 0
#define KSPLIT 2496  // K split boundary (multiple of 32; keeps 16B alignment)

// ---------------- scratch (device globals; zero-initialized) ---------------
__device__ __half g_xth[B_*C_*N_];    // x^T fp16 (B,C,N)
__device__ __half g_Wqh[C_*C_];
__device__ __half g_Wkh[C_*C_];
__device__ __half g_Wvh[C_*C_];
__device__ float  g_xr2[2][B_*M_*C_]; // split-K partial sums (fp32)
__device__ __half g_xrh[B_*M_*C_];    // LN output fp16
__device__ __half g_qh [B_*N_*C_];    // Q (pre-scaled by 1/sqrt(32)*log2e)
__device__ __half g_kh [B_*M_*C_];
__device__ __half g_vt [B_*C_*VST];   // V^T (B,C,Mpad)

// ---------------- helpers ---------------------------------------------------
__device__ __forceinline__ unsigned sm_u32(const void* p) {
    return (unsigned)__cvta_generic_to_shared(p);
}
__device__ __forceinline__ void ldsm4(unsigned addr, unsigned& r0, unsigned& r1,
                                      unsigned& r2, unsigned& r3) {
    asm volatile("ldmatrix.sync.aligned.m8n8.x4.shared.b16 {%0,%1,%2,%3}, [%4];"
                 : "=r"(r0), "=r"(r1), "=r"(r2), "=r"(r3) : "r"(addr));
}
__device__ __forceinline__ void mma16816(float* c, unsigned a0, unsigned a1,
                                         unsigned a2, unsigned a3,
                                         unsigned b0, unsigned b1) {
    asm volatile("mma.sync.aligned.m16n8k16.row.col.f32.f16.f16.f32 "
                 "{%0,%1,%2,%3}, {%4,%5,%6,%7}, {%8,%9}, {%0,%1,%2,%3};"
                 : "+f"(c[0]), "+f"(c[1]), "+f"(c[2]), "+f"(c[3])
                 : "r"(a0), "r"(a1), "r"(a2), "r"(a3), "r"(b0), "r"(b1));
}
// fp16-accumulate variant: C/D are 2 regs of packed half2
__device__ __forceinline__ void mma16816h(unsigned& c0, unsigned& c1,
                                          unsigned a0, unsigned a1,
                                          unsigned a2, unsigned a3,
                                          unsigned b0, unsigned b1) {
    asm volatile("mma.sync.aligned.m16n8k16.row.col.f16.f16.f16.f16 "
                 "{%0,%1}, {%2,%3,%4,%5}, {%6,%7}, {%0,%1};"
                 : "+r"(c0), "+r"(c1)
                 : "r"(a0), "r"(a1), "r"(a2), "r"(a3), "r"(b0), "r"(b1));
}
__device__ __forceinline__ unsigned pack2(float a, float b) {
    __half2 h = __floats2half2_rn(a, b);
    return *reinterpret_cast<unsigned*>(&h);
}
__device__ __forceinline__ unsigned h2ex2(unsigned x) {
    unsigned y;
    asm("ex2.approx.f16x2 %0, %1;" : "=r"(y) : "r"(x));
    return y;
}
__device__ __forceinline__ void cp16(void* dst_smem, const void* src, bool pred) {
    unsigned d = sm_u32(dst_smem);
    int sz = pred ? 16 : 0;
    asm volatile("cp.async.cg.shared.global [%0], [%1], 16, %2;"
                 :: "r"(d), "l"(src), "r"(sz));
}
__device__ __forceinline__ void cp_commit() {
    asm volatile("cp.async.commit_group;");
}
template <int NN>
__device__ __forceinline__ void cp_wait() {
    asm volatile("cp.async.wait_group %0;" :: "n"(NN));
}

// ===========================================================================
// Kernel 1: fused x-transpose + W converts
// ===========================================================================
#define TRX_CTAS 2512   // 8 * 157 * 2
__global__ __launch_bounds__(256) void k_pre(const float* __restrict__ x,
                                             const float* __restrict__ Wq,
                                             const float* __restrict__ Wk,
                                             const float* __restrict__ Wv) {
    __shared__ float tile[32][33];
    const int id = blockIdx.x;
    if (id < TRX_CTAS) {
        int c_idx = id & 7;
        int n_idx = (id >> 3) % 157;
        int b     = id / (8 * 157);
        int c0 = c_idx * 32, n0 = n_idx * 32;
        int tx = threadIdx.x & 31, ty = threadIdx.x >> 5;
        #pragma unroll
        for (int i = 0; i < 4; i++) {
            int n = n0 + ty + i * 8;
            tile[ty + i * 8][tx] = (n < N_) ? x[((size_t)b * N_ + n) * C_ + c0 + tx] : 0.f;
        }
        __syncthreads();
        #pragma unroll
        for (int i = 0; i < 4; i++) {
            int n = n0 + tx;
            int c = c0 + ty + i * 8;
            if (n < N_) g_xth[((size_t)b * C_ + c) * N_ + n] = __float2half(tile[tx][ty + i * 8]);
        }
    } else {
        int id2 = id - TRX_CTAS;
        int sel = id2 >> 7;
        int blk = id2 & 127;
        const float* in = (sel == 0) ? Wq : ((sel == 1) ? Wk : Wv);
        __half* out = (sel == 0) ? g_Wqh : ((sel == 1) ? g_Wkh : g_Wvh);
        int i = (blk * 256 + threadIdx.x) * 2;
        float2 v = *(const float2*)(in + i);
        *(__half2*)(out + i) = __floats2half2_rn(v.x, v.y);
    }
}

// ===========================================================================
// Kernel 2: merged [split-K reduce-GEMM] + Q-projection
//   reduce: 64-row x 256-col tiles, K split in two halves -> 160 CTAs,
//   3-stage cp.async pipeline, ONE __syncthreads per K-iteration.
// ===========================================================================
#define RED_CTAS 160     // 2 (kh) * 2 (b) * 40 (m-blocks)
#define PQ_CTAS  316
#define RED_SMEM 76800   // As 3*5120B + Bs 3*20480B

__device__ void reduce_part(char* dsm, const float* __restrict__ Wc, int id) {
    __half* As0 = (__half*)dsm;                  // 3 stages x 64*40 halves
    __half* Bs0 = (__half*)(dsm + 15360);        // 3 stages x 256*40 halves

    const int b  = id & 1;
    const int mb = (id >> 1) % 40;
    const int kh = id / 80;
    const int m0 = mb * 64;
    const int kbase = kh ? KSPLIT : 0;
    const int kend  = kh ? N_ : KSPLIT;
    const int ITERS = kh ? 79 : 78;              // ceil((kend-kbase)/32)
    const int t = threadIdx.x, lane = t & 31, w = t >> 5;
    const int wm = w >> 2, wn = w & 3;
    const __half* Bg = g_xth + (size_t)b * C_ * N_;
    float* outp = g_xr2[kh] + (size_t)b * M_ * C_;

    const int lr = t >> 2, ls = t & 3;

    float acc[2][8][4];
    #pragma unroll
    for (int i = 0; i < 2; i++)
        #pragma unroll
        for (int j = 0; j < 8; j++)
            #pragma unroll
            for (int q = 0; q < 4; q++) acc[i][j][q] = 0.f;

    float4 ar[2];
    auto ldgA = [&](int kit) {
        int gm = m0 + lr, gk = kbase + kit * 32 + ls * 8;
        if (gm < M_ && gk + 8 <= kend) {
            const float* p = Wc + (size_t)gm * N_ + gk;
            ar[0] = *(const float4*)(p);
            ar[1] = *(const float4*)(p + 4);
        } else {
            ar[0] = make_float4(0.f, 0.f, 0.f, 0.f);
            ar[1] = make_float4(0.f, 0.f, 0.f, 0.f);
        }
    };
    auto stsA = [&](int s) {
        uint4 v;
        v.x = pack2(ar[0].x, ar[0].y); v.y = pack2(ar[0].z, ar[0].w);
        v.z = pack2(ar[1].x, ar[1].y); v.w = pack2(ar[1].z, ar[1].w);
        *(uint4*)(As0 + s * 2560 + lr * 40 + ls * 8) = v;
    };
    auto cpB = [&](int kit, int s) {
        #pragma unroll
        for (int i = 0; i < 4; i++) {
            int u = t + 256 * i;
            int r = u >> 2, seg = u & 3;
            int gk = kbase + kit * 32 + seg * 8;
            cp16(Bs0 + s * 10240 + r * 40 + seg * 8,
                 Bg + (size_t)r * N_ + gk, gk + 8 <= kend);
        }
    };

    // prologue: stages 0 and 1 (ITERS >= 78 always)
    ldgA(0); stsA(0);
    ldgA(1); stsA(1);
    cpB(0, 0); cp_commit();
    cpB(1, 1); cp_commit();

    for (int tt = 0; tt < ITERS; tt++) {
        const int s = tt % 3;
        cp_wait<1>();
        __syncthreads();   // single barrier per iteration

        const bool pre = (tt + 2 < ITERS);
        if (pre) {
            cpB(tt + 2, (tt + 2) % 3);   // B prefetch (safe: all warps past sync)
            ldgA(tt + 2);                // start A LDG early; STS after MMAs
        }
        cp_commit();

        #pragma unroll
        for (int ks = 0; ks < 2; ks++) {
            unsigned a[2][4];
            #pragma unroll
            for (int mf = 0; mf < 2; mf++) {
                unsigned addr = sm_u32(As0 + s * 2560 + (wm * 32 + mf * 16 + (lane & 15)) * 40
                                       + ks * 16 + ((lane >> 4) << 3));
                ldsm4(addr, a[mf][0], a[mf][1], a[mf][2], a[mf][3]);
            }
            #pragma unroll
            for (int p = 0; p < 4; p++) {
                unsigned b0, b1, b2, b3;
                unsigned addr = sm_u32(Bs0 + s * 10240 + (wn * 64 + p * 16 + (lane & 15)) * 40
                                       + ks * 16 + ((lane >> 4) << 3));
                ldsm4(addr, b0, b1, b2, b3);
                #pragma unroll
                for (int mf = 0; mf < 2; mf++) {
                    mma16816(acc[mf][2 * p],     a[mf][0], a[mf][1], a[mf][2], a[mf][3], b0, b2);
                    mma16816(acc[mf][2 * p + 1], a[mf][0], a[mf][1], a[mf][2], a[mf][3], b1, b3);
                }
            }
        }
        if (pre) stsA((tt + 2) % 3);     // after MMAs so LDG latency overlaps
    }

    // store fp32 partials (no bias: bc cancels in the downstream LayerNorm)
    #pragma unroll
    for (int mf = 0; mf < 2; mf++) {
        #pragma unroll
        for (int hh = 0; hh < 2; hh++) {
            int r = m0 + wm * 32 + mf * 16 + (lane >> 2) + hh * 8;
            if (r >= M_) continue;
            #pragma unroll
            for (int nf = 0; nf < 8; nf++) {
                int c = wn * 64 + nf * 8 + (lane & 3) * 2;
                *(float2*)(outp + (size_t)r * C_ + c) =
                    make_float2(acc[mf][nf][hh * 2 + 0], acc[mf][nf][hh * 2 + 1]);
            }
        }
    }
}

__device__ void projQ_part(char* dsm, const float* __restrict__ x,
                           const float* __restrict__ bq, int id) {
    __half* As = (__half*)dsm;
    __half* Bs = (__half*)(dsm + 10240);

    const int r0 = (id >> 2) * 128;
    const int c0 = (id & 3) * 64;
    const int t = threadIdx.x, lane = t & 31, w = t >> 5;
    const int wm = w >> 1, wn = w & 1;
    const int R = B_ * N_;
    const float qscale = 0.17677669529663687f * 1.4426950408889634f;

    float acc[2][4][4];
    #pragma unroll
    for (int i = 0; i < 2; i++)
        #pragma unroll
        for (int j = 0; j < 4; j++)
            #pragma unroll
            for (int q = 0; q < 4; q++) acc[i][j][q] = 0.f;

    for (int k0 = 0; k0 < C_; k0 += 32) {
        #pragma unroll
        for (int i = 0; i < 2; i++) {
            int u = t + 256 * i;
            int r = u >> 2, s = u & 3;
            int gr = r0 + r;
            uint4 v = make_uint4(0, 0, 0, 0);
            if (gr < R) {
                const float* p = x + (size_t)gr * C_ + k0 + s * 8;
                float4 f0 = *(const float4*)(p);
                float4 f1 = *(const float4*)(p + 4);
                v.x = pack2(f0.x, f0.y); v.y = pack2(f0.z, f0.w);
                v.z = pack2(f1.x, f1.y); v.w = pack2(f1.z, f1.w);
            }
            *(uint4*)(As + r * 40 + s * 8) = v;
        }
        {
            int r = t >> 2, s = t & 3;
            uint4 v = *(const uint4*)(g_Wqh + (size_t)(c0 + r) * C_ + k0 + s * 8);
            *(uint4*)(Bs + r * 40 + s * 8) = v;
        }
        __syncthreads();
        #pragma unroll
        for (int ks = 0; ks < 2; ks++) {
            unsigned a[2][4];
            #pragma unroll
            for (int mf = 0; mf < 2; mf++) {
                unsigned addr = sm_u32(As + (wm * 32 + mf * 16 + (lane & 15)) * 40
                                       + ks * 16 + ((lane >> 4) << 3));
                ldsm4(addr, a[mf][0], a[mf][1], a[mf][2], a[mf][3]);
            }
            unsigned bf[2][4];
            #pragma unroll
            for (int p = 0; p < 2; p++) {
                unsigned addr = sm_u32(Bs + (wn * 32 + p * 16 + (lane & 15)) * 40
                                       + ks * 16 + ((lane >> 4) << 3));
                ldsm4(addr, bf[p][0], bf[p][1], bf[p][2], bf[p][3]);
            }
            #pragma unroll
            for (int mf = 0; mf < 2; mf++)
                #pragma unroll
                for (int p = 0; p < 2; p++) {
                    mma16816(acc[mf][2 * p],     a[mf][0], a[mf][1], a[mf][2], a[mf][3], bf[p][0], bf[p][2]);
                    mma16816(acc[mf][2 * p + 1], a[mf][0], a[mf][1], a[mf][2], a[mf][3], bf[p][1], bf[p][3]);
                }
        }
        __syncthreads();
    }
    #pragma unroll
    for (int mf = 0; mf < 2; mf++) {
        #pragma unroll
        for (int hh = 0; hh < 2; hh++) {
            int r = r0 + wm * 32 + mf * 16 + (lane >> 2) + hh * 8;
            if (r >= R) continue;
            #pragma unroll
            for (int nf = 0; nf < 4; nf++) {
                int c = c0 + wn * 32 + nf * 8 + (lane & 3) * 2;
                float v0 = (acc[mf][nf][hh * 2 + 0] + bq[c])     * qscale;
                float v1 = (acc[mf][nf][hh * 2 + 1] + bq[c + 1]) * qscale;
                *(__half2*)(g_qh + (size_t)r * C_ + c) = __floats2half2_rn(v0, v1);
            }
        }
    }
}

__global__ __launch_bounds__(256) void k_red_projQ(const float* __restrict__ Wc,
                                                   const float* __restrict__ x,
                                                   const float* __restrict__ bq) {
    extern __shared__ __align__(16) char dsm[];
    if (blockIdx.x < RED_CTAS) reduce_part(dsm, Wc, blockIdx.x);
    else                       projQ_part(dsm, x, bq, blockIdx.x - RED_CTAS);
}

// ===========================================================================
// Kernel 2b: sum split-K partials + LayerNorm -> g_xrh (warp per row)
// ===========================================================================
__global__ __launch_bounds__(256) void k_ln(const float* __restrict__ gamma,
                                            const float* __restrict__ beta) {
    const int row  = blockIdx.x * 8 + (threadIdx.x >> 5);
    const int lane = threadIdx.x & 31;
    const float* X0 = g_xr2[0] + (size_t)row * C_ + lane * 8;
    const float* X1 = g_xr2[1] + (size_t)row * C_ + lane * 8;
    float4 a0 = *(const float4*)(X0),     a1 = *(const float4*)(X0 + 4);
    float4 b0v = *(const float4*)(X1),    b1v = *(const float4*)(X1 + 4);
    float4 a  = make_float4(a0.x + b0v.x, a0.y + b0v.y, a0.z + b0v.z, a0.w + b0v.w);
    float4 bv = make_float4(a1.x + b1v.x, a1.y + b1v.y, a1.z + b1v.z, a1.w + b1v.w);

    float s  = a.x + a.y + a.z + a.w + bv.x + bv.y + bv.z + bv.w;
    float s2 = a.x*a.x + a.y*a.y + a.z*a.z + a.w*a.w
             + bv.x*bv.x + bv.y*bv.y + bv.z*bv.z + bv.w*bv.w;
    #pragma unroll
    for (int o = 16; o; o >>= 1) {
        s  += __shfl_xor_sync(0xffffffffu, s,  o);
        s2 += __shfl_xor_sync(0xffffffffu, s2, o);
    }
    float mu  = s * (1.f / 256.f);
    float var = s2 * (1.f / 256.f) - mu * mu;
    float rs  = rsqrtf(var + 1e-5f);

    const float* gp = gamma + lane * 8;
    const float* bp = beta  + lane * 8;
    float4 g0 = *(const float4*)(gp), g1 = *(const float4*)(gp + 4);
    float4 e0 = *(const float4*)(bp), e1 = *(const float4*)(bp + 4);

    uint4 outv;
    outv.x = pack2(g0.x*(a.x-mu)*rs + e0.x,  g0.y*(a.y-mu)*rs + e0.y);
    outv.y = pack2(g0.z*(a.z-mu)*rs + e0.z,  g0.w*(a.w-mu)*rs + e0.w);
    outv.z = pack2(g1.x*(bv.x-mu)*rs + e1.x, g1.y*(bv.y-mu)*rs + e1.y);
    outv.w = pack2(g1.z*(bv.z-mu)*rs + e1.z, g1.w*(bv.w-mu)*rs + e1.w);
    *(uint4*)(g_xrh + (size_t)row * C_ + lane * 8) = outv;
}

// ===========================================================================
// Kernel 3: K and V projections, 2-stage cp.async pipeline
// ===========================================================================
#define KV_CTAS 160
__global__ __launch_bounds__(256) void k_projKV(const float* __restrict__ bk,
                                                const float* __restrict__ bv) {
    __shared__ __align__(16) __half As[2][128 * 40];
    __shared__ __align__(16) __half Bs[2][64 * 40];

    const int id = blockIdx.x;
    const int mode = (id < KV_CTAS) ? 1 : 2;
    const int rid = (mode == 1) ? id : id - KV_CTAS;
    const int r0 = (rid >> 2) * 128;
    const int c0 = (rid & 3) * 64;
    const __half* W   = (mode == 1) ? g_Wkh : g_Wvh;
    const float* bias = (mode == 1) ? bk : bv;
    const int R = B_ * M_;

    const int t = threadIdx.x, lane = t & 31, w = t >> 5;
    const int wm = w >> 1, wn = w & 1;

    float acc[2][4][4];
    #pragma unroll
    for (int i = 0; i < 2; i++)
        #pragma unroll
        for (int j = 0; j < 4; j++)
            #pragma unroll
            for (int q = 0; q < 4; q++) acc[i][j][q] = 0.f;

    auto load_stage = [&](int k0, int buf) {
        #pragma unroll
        for (int i = 0; i < 2; i++) {
            int u = t + 256 * i;
            int r = u >> 2, s = u & 3;
            cp16(&As[buf][r * 40 + s * 8],
                 g_xrh + (size_t)(r0 + r) * C_ + k0 + s * 8, r0 + r < R);
        }
        {
            int r = t >> 2, s = t & 3;
            cp16(&Bs[buf][r * 40 + s * 8],
                 W + (size_t)(c0 + r) * C_ + k0 + s * 8, true);
        }
    };

    load_stage(0, 0);
    cp_commit();

    for (int it = 0; it < 8; it++) {
        int buf = it & 1;
        if (it + 1 < 8) load_stage((it + 1) * 32, buf ^ 1);
        cp_commit();
        cp_wait<1>();
        __syncthreads();
        #pragma unroll
        for (int ks = 0; ks < 2; ks++) {
            unsigned a[2][4];
            #pragma unroll
            for (int mf = 0; mf < 2; mf++) {
                unsigned addr = sm_u32(&As[buf][(wm * 32 + mf * 16 + (lane & 15)) * 40
                                       + ks * 16 + ((lane >> 4) << 3)]);
                ldsm4(addr, a[mf][0], a[mf][1], a[mf][2], a[mf][3]);
            }
            unsigned bf[2][4];
            #pragma unroll
            for (int p = 0; p < 2; p++) {
                unsigned addr = sm_u32(&Bs[buf][(wn * 32 + p * 16 + (lane & 15)) * 40
                                       + ks * 16 + ((lane >> 4) << 3)]);
                ldsm4(addr, bf[p][0], bf[p][1], bf[p][2], bf[p][3]);
            }
            #pragma unroll
            for (int mf = 0; mf < 2; mf++)
                #pragma unroll
                for (int p = 0; p < 2; p++) {
                    mma16816(acc[mf][2 * p],     a[mf][0], a[mf][1], a[mf][2], a[mf][3], bf[p][0], bf[p][2]);
                    mma16816(acc[mf][2 * p + 1], a[mf][0], a[mf][1], a[mf][2], a[mf][3], bf[p][1], bf[p][3]);
                }
        }
        __syncthreads();
    }
    #pragma unroll
    for (int mf = 0; mf < 2; mf++) {
        #pragma unroll
        for (int hh = 0; hh < 2; hh++) {
            int r = r0 + wm * 32 + mf * 16 + (lane >> 2) + hh * 8;
            if (r >= R) continue;
            #pragma unroll
            for (int nf = 0; nf < 4; nf++) {
                int c = c0 + wn * 32 + nf * 8 + (lane & 3) * 2;
                float v0 = acc[mf][nf][hh * 2 + 0] + bias[c];
                float v1 = acc[mf][nf][hh * 2 + 1] + bias[c + 1];
                if (mode == 1) {
                    *(__half2*)(g_kh + (size_t)r * C_ + c) = __floats2half2_rn(v0, v1);
                } else {
                    int bb = r / M_, m = r - bb * M_;
                    g_vt[((size_t)bb * C_ + c)     * VST + m] = __float2half(v0);
                    g_vt[((size_t)bb * C_ + c + 1) * VST + m] = __float2half(v1);
                }
            }
        }
    }
}

// ===========================================================================
// Kernel 4: flash attention — R11 configuration (best known): QK fp16-acc,
// ex2 in place, l via ones-MMA on tensor pipe, PV fp32-acc.
// ===========================================================================
#define NT2 20
#define ONES2 0x3C003C00u
#define NEGBIG2 0xDF00DF00u   // half2(-448, -448): ex2 -> 0
__global__ __launch_bounds__(128, 4) void k_attn(float* __restrict__ out) {
    __shared__ __half Ks[2][128 * 40];   // 10240 B each
    __shared__ __half Vt[2][32 * 136];   //  8704 B each

    const int b = blockIdx.z, h = blockIdx.y;
    const int t = threadIdx.x, lane = t & 31, w = t >> 5;
    const int n0 = blockIdx.x * 128;

    // stage Q (128 x 32) through Ks[0], then hold fragments in registers
    #pragma unroll
    for (int i = 0; i < 4; i++) {
        int u = t + 128 * i;
        int r = u >> 2, s = u & 3;
        cp16(&Ks[0][r * 40 + s * 8],
             g_qh + ((size_t)(b * N_ + n0 + r)) * C_ + h * 32 + s * 8, n0 + r < N_);
    }
    cp_commit();
    cp_wait<0>();
    __syncthreads();
    unsigned qa[2][2][4];   // [mf][ks]
    #pragma unroll
    for (int mf = 0; mf < 2; mf++)
        #pragma unroll
        for (int ks = 0; ks < 2; ks++) {
            unsigned addr = sm_u32(&Ks[0][(w * 32 + mf * 16 + (lane & 15)) * 40
                                   + ks * 16 + ((lane >> 4) << 3)]);
            ldsm4(addr, qa[mf][ks][0], qa[mf][ks][1], qa[mf][ks][2], qa[mf][ks][3]);
        }
    __syncthreads();   // all warps done with Q before Ks[0] is recycled

    const __half* Kg = g_kh + ((size_t)b * M_) * C_ + h * 32;
    const __half* Vg = g_vt + ((size_t)(b * C_ + h * 32)) * VST;
    auto load_kv = [&](int tile, int buf) {
        int m0 = tile * 128;
        #pragma unroll
        for (int i = 0; i < 4; i++) {
            int u = t + 128 * i;
            int r = u >> 2, s = u & 3;
            cp16(&Ks[buf][r * 40 + s * 8], Kg + (size_t)(m0 + r) * C_ + s * 8, m0 + r < M_);
        }
        #pragma unroll
        for (int i = 0; i < 4; i++) {
            int u = t + 128 * i;
            int r = u >> 4, s = u & 15;
            cp16(&Vt[buf][r * 136 + s * 8], Vg + (size_t)r * VST + m0 + s * 8, true);
        }
    };

    load_kv(0, 0);
    cp_commit();

    float lacc[2][4];
    #pragma unroll
    for (int mf = 0; mf < 2; mf++)
        #pragma unroll
        for (int j = 0; j < 4; j++) lacc[mf][j] = 0.f;
    float oacc[2][4][4];
    #pragma unroll
    for (int mf = 0; mf < 2; mf++)
        #pragma unroll
        for (int i = 0; i < 4; i++)
            #pragma unroll
            for (int j = 0; j < 4; j++) oacc[mf][i][j] = 0.f;

    const unsigned lane_off = (lane & 15) * 40 + ((lane >> 4) << 3);

    for (int tile = 0; tile < NT2; tile++) {
        const int buf = tile & 1;
        if (tile + 1 < NT2) load_kv(tile + 1, buf ^ 1);
        cp_commit();
        cp_wait<1>();
        __syncthreads();

        #pragma unroll
        for (int half = 0; half < 2; half++) {
            unsigned ph[2][8][2];
            // QK with fp16 accumulation: C fragment {c01, c23} is the packed P
            #pragma unroll
            for (int p = 0; p < 4; p++) {
                unsigned ch[2][2][2];   // [mf][f][reg]
                #pragma unroll
                for (int mf = 0; mf < 2; mf++)
                    #pragma unroll
                    for (int f = 0; f < 2; f++) {
                        ch[mf][f][0] = 0u; ch[mf][f][1] = 0u;
                    }
                #pragma unroll
                for (int ks = 0; ks < 2; ks++) {
                    unsigned bb0, bb1, bb2, bb3;
                    unsigned addr = sm_u32(&Ks[buf][(half * 64 + p * 16) * 40 + ks * 16]) + lane_off * 2;
                    ldsm4(addr, bb0, bb1, bb2, bb3);
                    #pragma unroll
                    for (int mf = 0; mf < 2; mf++) {
                        mma16816h(ch[mf][0][0], ch[mf][0][1], qa[mf][ks][0], qa[mf][ks][1],
                                  qa[mf][ks][2], qa[mf][ks][3], bb0, bb2);
                        mma16816h(ch[mf][1][0], ch[mf][1][1], qa[mf][ks][0], qa[mf][ks][1],
                                  qa[mf][ks][2], qa[mf][ks][3], bb1, bb3);
                    }
                }
                // mask tail keys (M_ even => key pairs never straddle the edge)
                if (tile == NT2 - 1) {
                    #pragma unroll
                    for (int f = 0; f < 2; f++) {
                        int key = tile * 128 + half * 64 + (p * 2 + f) * 8 + (lane & 3) * 2;
                        if (key >= M_) {
                            #pragma unroll
                            for (int mf = 0; mf < 2; mf++) {
                                ch[mf][f][0] = NEGBIG2; ch[mf][f][1] = NEGBIG2;
                            }
                        }
                    }
                }
                #pragma unroll
                for (int mf = 0; mf < 2; mf++)
                    #pragma unroll
                    for (int f = 0; f < 2; f++) {
                        ph[mf][p * 2 + f][0] = h2ex2(ch[mf][f][0]);
                        ph[mf][p * 2 + f][1] = h2ex2(ch[mf][f][1]);
                    }
            }
            // O += P V ; l += P @ ones  (fp32 accumulate)
            #pragma unroll
            for (int kk = 0; kk < 4; kk++) {
                #pragma unroll
                for (int mf = 0; mf < 2; mf++)
                    mma16816(lacc[mf], ph[mf][2 * kk][0], ph[mf][2 * kk][1],
                             ph[mf][2 * kk + 1][0], ph[mf][2 * kk + 1][1], ONES2, ONES2);
                #pragma unroll
                for (int p = 0; p < 2; p++) {
                    unsigned bb0, bb1, bb2, bb3;
                    unsigned addr = sm_u32(&Vt[buf][(p * 16 + (lane & 15)) * 136
                                           + (half * 4 + kk) * 16 + ((lane >> 4) << 3)]);
                    ldsm4(addr, bb0, bb1, bb2, bb3);
                    #pragma unroll
                    for (int mf = 0; mf < 2; mf++) {
                        mma16816(oacc[mf][2 * p],     ph[mf][2 * kk][0], ph[mf][2 * kk][1],
                                 ph[mf][2 * kk + 1][0], ph[mf][2 * kk + 1][1], bb0, bb2);
                        mma16816(oacc[mf][2 * p + 1], ph[mf][2 * kk][0], ph[mf][2 * kk][1],
                                 ph[mf][2 * kk + 1][0], ph[mf][2 * kk + 1][1], bb1, bb3);
                    }
                }
            }
        }
        __syncthreads();
    }

    #pragma unroll
    for (int mf = 0; mf < 2; mf++) {
        float inv0 = 1.f / lacc[mf][0];
        float inv1 = 1.f / lacc[mf][2];
        int r = n0 + w * 32 + mf * 16 + (lane >> 2);
        #pragma unroll
        for (int nf = 0; nf < 4; nf++) {
            int d = h * 32 + nf * 8 + (lane & 3) * 2;
            if (r < N_) {
                *(float2*)(out + ((size_t)(b * N_ + r)) * C_ + d) =
                    make_float2(oacc[mf][nf][0] * inv0, oacc[mf][nf][1] * inv0);
            }
            if (r + 8 < N_) {
                *(float2*)(out + ((size_t)(b * N_ + r + 8)) * C_ + d) =
                    make_float2(oacc[mf][nf][2] * inv1, oacc[mf][nf][3] * inv1);
            }
        }
    }
}

// ---------------------------------------------------------------------------
extern "C" void kernel_launch(void* const* d_in, const int* in_sizes, int n_in,
                              void* d_out, int out_size) {
    (void)in_sizes; (void)n_in; (void)out_size;
    const float* x     = (const float*)d_in[0];
    const float* Wq    = (const float*)d_in[1];
    const float* bq    = (const float*)d_in[2];
    const float* Wk    = (const float*)d_in[3];
    const float* bk    = (const float*)d_in[4];
    const float* Wv    = (const float*)d_in[5];
    const float* bv    = (const float*)d_in[6];
    const float* Wc    = (const float*)d_in[7];
    const float* gamma = (const float*)d_in[9];
    const float* beta  = (const float*)d_in[10];
    float* out = (float*)d_out;

    static bool attr_done = false;
    if (!attr_done) {
        cudaFuncSetAttribute(k_red_projQ, cudaFuncAttributeMaxDynamicSharedMemorySize,
                             RED_SMEM);
        attr_done = true;
    }

    k_pre<<<TRX_CTAS + 384, 256>>>(x, Wq, Wk, Wv);
    k_red_projQ<<<RED_CTAS + PQ_CTAS, 256, RED_SMEM>>>(Wc, x, bq);
    k_ln<<<B_ * M_ / 8, 256>>>(gamma, beta);
    k_projKV<<<2 * KV_CTAS, 256>>>(bk, bv);
    dim3 ga((N_ + 127) / 128, H_, B_);
    k_attn<<<ga, 128>>>(out);
}

// round 17
// speedup vs baseline: 1.3230x; 1.0816x over previous
#include <cuda_runtime.h>
#include <cuda_fp16.h>

#define B_  2
#define N_  5000
#define C_  256
#define H_  8
#define M_  2500
#define DK_ 32
#define VST 2560   // padded M stride for g_vt, pad stays 0
#define KQ  1248   // K quarter size (multiple of 32; keeps 16B alignment)

// ---------------- scratch (device globals; zero-initialized) ---------------
__device__ __half g_xth[B_*C_*N_];    // x^T fp16 (B,C,N)
__device__ __half g_Wqh[C_*C_];
__device__ __half g_Wkh[C_*C_];
__device__ __half g_Wvh[C_*C_];
__device__ float  g_xr2[4][B_*M_*C_]; // split-K partial sums (fp32)
__device__ __half g_xrh[B_*M_*C_];    // LN output fp16
__device__ __half g_qh [B_*N_*C_];    // Q (pre-scaled by 1/sqrt(32)*log2e)
__device__ __half g_kh [B_*M_*C_];
__device__ __half g_vt [B_*C_*VST];   // V^T (B,C,Mpad)

// ---------------- helpers ---------------------------------------------------
__device__ __forceinline__ unsigned sm_u32(const void* p) {
    return (unsigned)__cvta_generic_to_shared(p);
}
__device__ __forceinline__ void ldsm4(unsigned addr, unsigned& r0, unsigned& r1,
                                      unsigned& r2, unsigned& r3) {
    asm volatile("ldmatrix.sync.aligned.m8n8.x4.shared.b16 {%0,%1,%2,%3}, [%4];"
                 : "=r"(r0), "=r"(r1), "=r"(r2), "=r"(r3) : "r"(addr));
}
__device__ __forceinline__ void mma16816(float* c, unsigned a0, unsigned a1,
                                         unsigned a2, unsigned a3,
                                         unsigned b0, unsigned b1) {
    asm volatile("mma.sync.aligned.m16n8k16.row.col.f32.f16.f16.f32 "
                 "{%0,%1,%2,%3}, {%4,%5,%6,%7}, {%8,%9}, {%0,%1,%2,%3};"
                 : "+f"(c[0]), "+f"(c[1]), "+f"(c[2]), "+f"(c[3])
                 : "r"(a0), "r"(a1), "r"(a2), "r"(a3), "r"(b0), "r"(b1));
}
// fp16-accumulate variant: C/D are 2 regs of packed half2
__device__ __forceinline__ void mma16816h(unsigned& c0, unsigned& c1,
                                          unsigned a0, unsigned a1,
                                          unsigned a2, unsigned a3,
                                          unsigned b0, unsigned b1) {
    asm volatile("mma.sync.aligned.m16n8k16.row.col.f16.f16.f16.f16 "
                 "{%0,%1}, {%2,%3,%4,%5}, {%6,%7}, {%0,%1};"
                 : "+r"(c0), "+r"(c1)
                 : "r"(a0), "r"(a1), "r"(a2), "r"(a3), "r"(b0), "r"(b1));
}
__device__ __forceinline__ unsigned pack2(float a, float b) {
    __half2 h = __floats2half2_rn(a, b);
    return *reinterpret_cast<unsigned*>(&h);
}
__device__ __forceinline__ unsigned h2ex2(unsigned x) {
    unsigned y;
    asm("ex2.approx.f16x2 %0, %1;" : "=r"(y) : "r"(x));
    return y;
}
__device__ __forceinline__ void cp16(void* dst_smem, const void* src, bool pred) {
    unsigned d = sm_u32(dst_smem);
    int sz = pred ? 16 : 0;
    asm volatile("cp.async.cg.shared.global [%0], [%1], 16, %2;"
                 :: "r"(d), "l"(src), "r"(sz));
}
__device__ __forceinline__ void cp_commit() {
    asm volatile("cp.async.commit_group;");
}
template <int NN>
__device__ __forceinline__ void cp_wait() {
    asm volatile("cp.async.wait_group %0;" :: "n"(NN));
}

// ===========================================================================
// Kernel 1: fused x-transpose + W converts
// ===========================================================================
#define TRX_CTAS 2512   // 8 * 157 * 2
__global__ __launch_bounds__(256) void k_pre(const float* __restrict__ x,
                                             const float* __restrict__ Wq,
                                             const float* __restrict__ Wk,
                                             const float* __restrict__ Wv) {
    __shared__ float tile[32][33];
    const int id = blockIdx.x;
    if (id < TRX_CTAS) {
        int c_idx = id & 7;
        int n_idx = (id >> 3) % 157;
        int b     = id / (8 * 157);
        int c0 = c_idx * 32, n0 = n_idx * 32;
        int tx = threadIdx.x & 31, ty = threadIdx.x >> 5;
        #pragma unroll
        for (int i = 0; i < 4; i++) {
            int n = n0 + ty + i * 8;
            tile[ty + i * 8][tx] = (n < N_) ? x[((size_t)b * N_ + n) * C_ + c0 + tx] : 0.f;
        }
        __syncthreads();
        #pragma unroll
        for (int i = 0; i < 4; i++) {
            int n = n0 + tx;
            int c = c0 + ty + i * 8;
            if (n < N_) g_xth[((size_t)b * C_ + c) * N_ + n] = __float2half(tile[tx][ty + i * 8]);
        }
    } else {
        int id2 = id - TRX_CTAS;
        int sel = id2 >> 7;
        int blk = id2 & 127;
        const float* in = (sel == 0) ? Wq : ((sel == 1) ? Wk : Wv);
        __half* out = (sel == 0) ? g_Wqh : ((sel == 1) ? g_Wkh : g_Wvh);
        int i = (blk * 256 + threadIdx.x) * 2;
        float2 v = *(const float2*)(in + i);
        *(__half2*)(out + i) = __floats2half2_rn(v.x, v.y);
    }
}

// ===========================================================================
// Kernel 2: merged [4-way split-K reduce-GEMM] + Q-projection
//   reduce: 64-row x 256-col tiles, K in four quarters -> 320 CTAs,
//   3-stage cp.async pipeline, ONE __syncthreads per K-iteration.
// ===========================================================================
#define RED_CTAS 320     // 4 (kh) * 2 (b) * 40 (m-blocks)
#define PQ_CTAS  316
#define RED_SMEM 76800   // As 3*5120B + Bs 3*20480B

__device__ void reduce_part(char* dsm, const float* __restrict__ Wc, int id) {
    __half* As0 = (__half*)dsm;                  // 3 stages x 64*40 halves
    __half* Bs0 = (__half*)(dsm + 15360);        // 3 stages x 256*40 halves

    const int b  = id & 1;
    const int mb = (id >> 1) % 40;
    const int kh = id / 80;
    const int m0 = mb * 64;
    const int kbase = kh * KQ;
    const int kend  = (kh == 3) ? N_ : kbase + KQ;
    const int ITERS = (kend - kbase + 31) / 32;  // 39 or 40
    const int t = threadIdx.x, lane = t & 31, w = t >> 5;
    const int wm = w >> 2, wn = w & 3;
    const __half* Bg = g_xth + (size_t)b * C_ * N_;
    float* outp = g_xr2[kh] + (size_t)b * M_ * C_;

    const int lr = t >> 2, ls = t & 3;

    float acc[2][8][4];
    #pragma unroll
    for (int i = 0; i < 2; i++)
        #pragma unroll
        for (int j = 0; j < 8; j++)
            #pragma unroll
            for (int q = 0; q < 4; q++) acc[i][j][q] = 0.f;

    float4 ar[2];
    auto ldgA = [&](int kit) {
        int gm = m0 + lr, gk = kbase + kit * 32 + ls * 8;
        if (gm < M_ && gk + 8 <= kend) {
            const float* p = Wc + (size_t)gm * N_ + gk;
            ar[0] = *(const float4*)(p);
            ar[1] = *(const float4*)(p + 4);
        } else {
            ar[0] = make_float4(0.f, 0.f, 0.f, 0.f);
            ar[1] = make_float4(0.f, 0.f, 0.f, 0.f);
        }
    };
    auto stsA = [&](int s) {
        uint4 v;
        v.x = pack2(ar[0].x, ar[0].y); v.y = pack2(ar[0].z, ar[0].w);
        v.z = pack2(ar[1].x, ar[1].y); v.w = pack2(ar[1].z, ar[1].w);
        *(uint4*)(As0 + s * 2560 + lr * 40 + ls * 8) = v;
    };
    auto cpB = [&](int kit, int s) {
        #pragma unroll
        for (int i = 0; i < 4; i++) {
            int u = t + 256 * i;
            int r = u >> 2, seg = u & 3;
            int gk = kbase + kit * 32 + seg * 8;
            cp16(Bs0 + s * 10240 + r * 40 + seg * 8,
                 Bg + (size_t)r * N_ + gk, gk + 8 <= kend);
        }
    };

    // prologue: stages 0 and 1 (ITERS >= 39 always)
    ldgA(0); stsA(0);
    ldgA(1); stsA(1);
    cpB(0, 0); cp_commit();
    cpB(1, 1); cp_commit();

    for (int tt = 0; tt < ITERS; tt++) {
        const int s = tt % 3;
        cp_wait<1>();
        __syncthreads();   // single barrier per iteration

        const bool pre = (tt + 2 < ITERS);
        if (pre) {
            cpB(tt + 2, (tt + 2) % 3);   // B prefetch (safe: all warps past sync)
            ldgA(tt + 2);                // start A LDG early; STS after MMAs
        }
        cp_commit();

        #pragma unroll
        for (int ks = 0; ks < 2; ks++) {
            unsigned a[2][4];
            #pragma unroll
            for (int mf = 0; mf < 2; mf++) {
                unsigned addr = sm_u32(As0 + s * 2560 + (wm * 32 + mf * 16 + (lane & 15)) * 40
                                       + ks * 16 + ((lane >> 4) << 3));
                ldsm4(addr, a[mf][0], a[mf][1], a[mf][2], a[mf][3]);
            }
            #pragma unroll
            for (int p = 0; p < 4; p++) {
                unsigned b0, b1, b2, b3;
                unsigned addr = sm_u32(Bs0 + s * 10240 + (wn * 64 + p * 16 + (lane & 15)) * 40
                                       + ks * 16 + ((lane >> 4) << 3));
                ldsm4(addr, b0, b1, b2, b3);
                #pragma unroll
                for (int mf = 0; mf < 2; mf++) {
                    mma16816(acc[mf][2 * p],     a[mf][0], a[mf][1], a[mf][2], a[mf][3], b0, b2);
                    mma16816(acc[mf][2 * p + 1], a[mf][0], a[mf][1], a[mf][2], a[mf][3], b1, b3);
                }
            }
        }
        if (pre) stsA((tt + 2) % 3);     // after MMAs so LDG latency overlaps
    }

    // store fp32 partials (no bias: bc cancels in the downstream LayerNorm)
    #pragma unroll
    for (int mf = 0; mf < 2; mf++) {
        #pragma unroll
        for (int hh = 0; hh < 2; hh++) {
            int r = m0 + wm * 32 + mf * 16 + (lane >> 2) + hh * 8;
            if (r >= M_) continue;
            #pragma unroll
            for (int nf = 0; nf < 8; nf++) {
                int c = wn * 64 + nf * 8 + (lane & 3) * 2;
                *(float2*)(outp + (size_t)r * C_ + c) =
                    make_float2(acc[mf][nf][hh * 2 + 0], acc[mf][nf][hh * 2 + 1]);
            }
        }
    }
}

__device__ void projQ_part(char* dsm, const float* __restrict__ x,
                           const float* __restrict__ bq, int id) {
    __half* As = (__half*)dsm;
    __half* Bs = (__half*)(dsm + 10240);

    const int r0 = (id >> 2) * 128;
    const int c0 = (id & 3) * 64;
    const int t = threadIdx.x, lane = t & 31, w = t >> 5;
    const int wm = w >> 1, wn = w & 1;
    const int R = B_ * N_;
    const float qscale = 0.17677669529663687f * 1.4426950408889634f;

    float acc[2][4][4];
    #pragma unroll
    for (int i = 0; i < 2; i++)
        #pragma unroll
        for (int j = 0; j < 4; j++)
            #pragma unroll
            for (int q = 0; q < 4; q++) acc[i][j][q] = 0.f;

    for (int k0 = 0; k0 < C_; k0 += 32) {
        #pragma unroll
        for (int i = 0; i < 2; i++) {
            int u = t + 256 * i;
            int r = u >> 2, s = u & 3;
            int gr = r0 + r;
            uint4 v = make_uint4(0, 0, 0, 0);
            if (gr < R) {
                const float* p = x + (size_t)gr * C_ + k0 + s * 8;
                float4 f0 = *(const float4*)(p);
                float4 f1 = *(const float4*)(p + 4);
                v.x = pack2(f0.x, f0.y); v.y = pack2(f0.z, f0.w);
                v.z = pack2(f1.x, f1.y); v.w = pack2(f1.z, f1.w);
            }
            *(uint4*)(As + r * 40 + s * 8) = v;
        }
        {
            int r = t >> 2, s = t & 3;
            uint4 v = *(const uint4*)(g_Wqh + (size_t)(c0 + r) * C_ + k0 + s * 8);
            *(uint4*)(Bs + r * 40 + s * 8) = v;
        }
        __syncthreads();
        #pragma unroll
        for (int ks = 0; ks < 2; ks++) {
            unsigned a[2][4];
            #pragma unroll
            for (int mf = 0; mf < 2; mf++) {
                unsigned addr = sm_u32(As + (wm * 32 + mf * 16 + (lane & 15)) * 40
                                       + ks * 16 + ((lane >> 4) << 3));
                ldsm4(addr, a[mf][0], a[mf][1], a[mf][2], a[mf][3]);
            }
            unsigned bf[2][4];
            #pragma unroll
            for (int p = 0; p < 2; p++) {
                unsigned addr = sm_u32(Bs + (wn * 32 + p * 16 + (lane & 15)) * 40
                                       + ks * 16 + ((lane >> 4) << 3));
                ldsm4(addr, bf[p][0], bf[p][1], bf[p][2], bf[p][3]);
            }
            #pragma unroll
            for (int mf = 0; mf < 2; mf++)
                #pragma unroll
                for (int p = 0; p < 2; p++) {
                    mma16816(acc[mf][2 * p],     a[mf][0], a[mf][1], a[mf][2], a[mf][3], bf[p][0], bf[p][2]);
                    mma16816(acc[mf][2 * p + 1], a[mf][0], a[mf][1], a[mf][2], a[mf][3], bf[p][1], bf[p][3]);
                }
        }
        __syncthreads();
    }
    #pragma unroll
    for (int mf = 0; mf < 2; mf++) {
        #pragma unroll
        for (int hh = 0; hh < 2; hh++) {
            int r = r0 + wm * 32 + mf * 16 + (lane >> 2) + hh * 8;
            if (r >= R) continue;
            #pragma unroll
            for (int nf = 0; nf < 4; nf++) {
                int c = c0 + wn * 32 + nf * 8 + (lane & 3) * 2;
                float v0 = (acc[mf][nf][hh * 2 + 0] + bq[c])     * qscale;
                float v1 = (acc[mf][nf][hh * 2 + 1] + bq[c + 1]) * qscale;
                *(__half2*)(g_qh + (size_t)r * C_ + c) = __floats2half2_rn(v0, v1);
            }
        }
    }
}

__global__ __launch_bounds__(256) void k_red_projQ(const float* __restrict__ Wc,
                                                   const float* __restrict__ x,
                                                   const float* __restrict__ bq) {
    extern __shared__ __align__(16) char dsm[];
    if (blockIdx.x < RED_CTAS) reduce_part(dsm, Wc, blockIdx.x);
    else                       projQ_part(dsm, x, bq, blockIdx.x - RED_CTAS);
}

// ===========================================================================
// Kernel 2b: sum split-K partials + LayerNorm -> g_xrh (warp per row)
// ===========================================================================
__global__ __launch_bounds__(256) void k_ln(const float* __restrict__ gamma,
                                            const float* __restrict__ beta) {
    const int row  = blockIdx.x * 8 + (threadIdx.x >> 5);
    const int lane = threadIdx.x & 31;
    const size_t off = (size_t)row * C_ + lane * 8;
    float4 a  = make_float4(0.f, 0.f, 0.f, 0.f);
    float4 bv = make_float4(0.f, 0.f, 0.f, 0.f);
    #pragma unroll
    for (int kh = 0; kh < 4; kh++) {
        const float* X = g_xr2[kh] + off;
        float4 p0 = *(const float4*)(X);
        float4 p1 = *(const float4*)(X + 4);
        a.x += p0.x; a.y += p0.y; a.z += p0.z; a.w += p0.w;
        bv.x += p1.x; bv.y += p1.y; bv.z += p1.z; bv.w += p1.w;
    }

    float s  = a.x + a.y + a.z + a.w + bv.x + bv.y + bv.z + bv.w;
    float s2 = a.x*a.x + a.y*a.y + a.z*a.z + a.w*a.w
             + bv.x*bv.x + bv.y*bv.y + bv.z*bv.z + bv.w*bv.w;
    #pragma unroll
    for (int o = 16; o; o >>= 1) {
        s  += __shfl_xor_sync(0xffffffffu, s,  o);
        s2 += __shfl_xor_sync(0xffffffffu, s2, o);
    }
    float mu  = s * (1.f / 256.f);
    float var = s2 * (1.f / 256.f) - mu * mu;
    float rs  = rsqrtf(var + 1e-5f);

    const float* gp = gamma + lane * 8;
    const float* bp = beta  + lane * 8;
    float4 g0 = *(const float4*)(gp), g1 = *(const float4*)(gp + 4);
    float4 e0 = *(const float4*)(bp), e1 = *(const float4*)(bp + 4);

    uint4 outv;
    outv.x = pack2(g0.x*(a.x-mu)*rs + e0.x,  g0.y*(a.y-mu)*rs + e0.y);
    outv.y = pack2(g0.z*(a.z-mu)*rs + e0.z,  g0.w*(a.w-mu)*rs + e0.w);
    outv.z = pack2(g1.x*(bv.x-mu)*rs + e1.x, g1.y*(bv.y-mu)*rs + e1.y);
    outv.w = pack2(g1.z*(bv.z-mu)*rs + e1.z, g1.w*(bv.w-mu)*rs + e1.w);
    *(uint4*)(g_xrh + (size_t)row * C_ + lane * 8) = outv;
}

// ===========================================================================
// Kernel 3: K and V projections, 2-stage cp.async pipeline
// ===========================================================================
#define KV_CTAS 160
__global__ __launch_bounds__(256) void k_projKV(const float* __restrict__ bk,
                                                const float* __restrict__ bv) {
    __shared__ __align__(16) __half As[2][128 * 40];
    __shared__ __align__(16) __half Bs[2][64 * 40];

    const int id = blockIdx.x;
    const int mode = (id < KV_CTAS) ? 1 : 2;
    const int rid = (mode == 1) ? id : id - KV_CTAS;
    const int r0 = (rid >> 2) * 128;
    const int c0 = (rid & 3) * 64;
    const __half* W   = (mode == 1) ? g_Wkh : g_Wvh;
    const float* bias = (mode == 1) ? bk : bv;
    const int R = B_ * M_;

    const int t = threadIdx.x, lane = t & 31, w = t >> 5;
    const int wm = w >> 1, wn = w & 1;

    float acc[2][4][4];
    #pragma unroll
    for (int i = 0; i < 2; i++)
        #pragma unroll
        for (int j = 0; j < 4; j++)
            #pragma unroll
            for (int q = 0; q < 4; q++) acc[i][j][q] = 0.f;

    auto load_stage = [&](int k0, int buf) {
        #pragma unroll
        for (int i = 0; i < 2; i++) {
            int u = t + 256 * i;
            int r = u >> 2, s = u & 3;
            cp16(&As[buf][r * 40 + s * 8],
                 g_xrh + (size_t)(r0 + r) * C_ + k0 + s * 8, r0 + r < R);
        }
        {
            int r = t >> 2, s = t & 3;
            cp16(&Bs[buf][r * 40 + s * 8],
                 W + (size_t)(c0 + r) * C_ + k0 + s * 8, true);
        }
    };

    load_stage(0, 0);
    cp_commit();

    for (int it = 0; it < 8; it++) {
        int buf = it & 1;
        if (it + 1 < 8) load_stage((it + 1) * 32, buf ^ 1);
        cp_commit();
        cp_wait<1>();
        __syncthreads();
        #pragma unroll
        for (int ks = 0; ks < 2; ks++) {
            unsigned a[2][4];
            #pragma unroll
            for (int mf = 0; mf < 2; mf++) {
                unsigned addr = sm_u32(&As[buf][(wm * 32 + mf * 16 + (lane & 15)) * 40
                                       + ks * 16 + ((lane >> 4) << 3)]);
                ldsm4(addr, a[mf][0], a[mf][1], a[mf][2], a[mf][3]);
            }
            unsigned bf[2][4];
            #pragma unroll
            for (int p = 0; p < 2; p++) {
                unsigned addr = sm_u32(&Bs[buf][(wn * 32 + p * 16 + (lane & 15)) * 40
                                       + ks * 16 + ((lane >> 4) << 3)]);
                ldsm4(addr, bf[p][0], bf[p][1], bf[p][2], bf[p][3]);
            }
            #pragma unroll
            for (int mf = 0; mf < 2; mf++)
                #pragma unroll
                for (int p = 0; p < 2; p++) {
                    mma16816(acc[mf][2 * p],     a[mf][0], a[mf][1], a[mf][2], a[mf][3], bf[p][0], bf[p][2]);
                    mma16816(acc[mf][2 * p + 1], a[mf][0], a[mf][1], a[mf][2], a[mf][3], bf[p][1], bf[p][3]);
                }
        }
        __syncthreads();
    }
    #pragma unroll
    for (int mf = 0; mf < 2; mf++) {
        #pragma unroll
        for (int hh = 0; hh < 2; hh++) {
            int r = r0 + wm * 32 + mf * 16 + (lane >> 2) + hh * 8;
            if (r >= R) continue;
            #pragma unroll
            for (int nf = 0; nf < 4; nf++) {
                int c = c0 + wn * 32 + nf * 8 + (lane & 3) * 2;
                float v0 = acc[mf][nf][hh * 2 + 0] + bias[c];
                float v1 = acc[mf][nf][hh * 2 + 1] + bias[c + 1];
                if (mode == 1) {
                    *(__half2*)(g_kh + (size_t)r * C_ + c) = __floats2half2_rn(v0, v1);
                } else {
                    int bb = r / M_, m = r - bb * M_;
                    g_vt[((size_t)bb * C_ + c)     * VST + m] = __float2half(v0);
                    g_vt[((size_t)bb * C_ + c + 1) * VST + m] = __float2half(v1);
                }
            }
        }
    }
}

// ===========================================================================
// Kernel 4: flash attention — best known config: QK fp16-acc, ex2 in place,
// l via ones-MMA on tensor pipe, PV fp32-acc.
// ===========================================================================
#define NT2 20
#define ONES2 0x3C003C00u
#define NEGBIG2 0xDF00DF00u   // half2(-448, -448): ex2 -> 0
__global__ __launch_bounds__(128, 4) void k_attn(float* __restrict__ out) {
    __shared__ __half Ks[2][128 * 40];   // 10240 B each
    __shared__ __half Vt[2][32 * 136];   //  8704 B each

    const int b = blockIdx.z, h = blockIdx.y;
    const int t = threadIdx.x, lane = t & 31, w = t >> 5;
    const int n0 = blockIdx.x * 128;

    // stage Q (128 x 32) through Ks[0], then hold fragments in registers
    #pragma unroll
    for (int i = 0; i < 4; i++) {
        int u = t + 128 * i;
        int r = u >> 2, s = u & 3;
        cp16(&Ks[0][r * 40 + s * 8],
             g_qh + ((size_t)(b * N_ + n0 + r)) * C_ + h * 32 + s * 8, n0 + r < N_);
    }
    cp_commit();
    cp_wait<0>();
    __syncthreads();
    unsigned qa[2][2][4];   // [mf][ks]
    #pragma unroll
    for (int mf = 0; mf < 2; mf++)
        #pragma unroll
        for (int ks = 0; ks < 2; ks++) {
            unsigned addr = sm_u32(&Ks[0][(w * 32 + mf * 16 + (lane & 15)) * 40
                                   + ks * 16 + ((lane >> 4) << 3)]);
            ldsm4(addr, qa[mf][ks][0], qa[mf][ks][1], qa[mf][ks][2], qa[mf][ks][3]);
        }
    __syncthreads();   // all warps done with Q before Ks[0] is recycled

    const __half* Kg = g_kh + ((size_t)b * M_) * C_ + h * 32;
    const __half* Vg = g_vt + ((size_t)(b * C_ + h * 32)) * VST;
    auto load_kv = [&](int tile, int buf) {
        int m0 = tile * 128;
        #pragma unroll
        for (int i = 0; i < 4; i++) {
            int u = t + 128 * i;
            int r = u >> 2, s = u & 3;
            cp16(&Ks[buf][r * 40 + s * 8], Kg + (size_t)(m0 + r) * C_ + s * 8, m0 + r < M_);
        }
        #pragma unroll
        for (int i = 0; i < 4; i++) {
            int u = t + 128 * i;
            int r = u >> 4, s = u & 15;
            cp16(&Vt[buf][r * 136 + s * 8], Vg + (size_t)r * VST + m0 + s * 8, true);
        }
    };

    load_kv(0, 0);
    cp_commit();

    float lacc[2][4];
    #pragma unroll
    for (int mf = 0; mf < 2; mf++)
        #pragma unroll
        for (int j = 0; j < 4; j++) lacc[mf][j] = 0.f;
    float oacc[2][4][4];
    #pragma unroll
    for (int mf = 0; mf < 2; mf++)
        #pragma unroll
        for (int i = 0; i < 4; i++)
            #pragma unroll
            for (int j = 0; j < 4; j++) oacc[mf][i][j] = 0.f;

    const unsigned lane_off = (lane & 15) * 40 + ((lane >> 4) << 3);

    for (int tile = 0; tile < NT2; tile++) {
        const int buf = tile & 1;
        if (tile + 1 < NT2) load_kv(tile + 1, buf ^ 1);
        cp_commit();
        cp_wait<1>();
        __syncthreads();

        #pragma unroll
        for (int half = 0; half < 2; half++) {
            unsigned ph[2][8][2];
            // QK with fp16 accumulation: C fragment {c01, c23} is the packed P
            #pragma unroll
            for (int p = 0; p < 4; p++) {
                unsigned ch[2][2][2];   // [mf][f][reg]
                #pragma unroll
                for (int mf = 0; mf < 2; mf++)
                    #pragma unroll
                    for (int f = 0; f < 2; f++) {
                        ch[mf][f][0] = 0u; ch[mf][f][1] = 0u;
                    }
                #pragma unroll
                for (int ks = 0; ks < 2; ks++) {
                    unsigned bb0, bb1, bb2, bb3;
                    unsigned addr = sm_u32(&Ks[buf][(half * 64 + p * 16) * 40 + ks * 16]) + lane_off * 2;
                    ldsm4(addr, bb0, bb1, bb2, bb3);
                    #pragma unroll
                    for (int mf = 0; mf < 2; mf++) {
                        mma16816h(ch[mf][0][0], ch[mf][0][1], qa[mf][ks][0], qa[mf][ks][1],
                                  qa[mf][ks][2], qa[mf][ks][3], bb0, bb2);
                        mma16816h(ch[mf][1][0], ch[mf][1][1], qa[mf][ks][0], qa[mf][ks][1],
                                  qa[mf][ks][2], qa[mf][ks][3], bb1, bb3);
                    }
                }
                // mask tail keys (M_ even => key pairs never straddle the edge)
                if (tile == NT2 - 1) {
                    #pragma unroll
                    for (int f = 0; f < 2; f++) {
                        int key = tile * 128 + half * 64 + (p * 2 + f) * 8 + (lane & 3) * 2;
                        if (key >= M_) {
                            #pragma unroll
                            for (int mf = 0; mf < 2; mf++) {
                                ch[mf][f][0] = NEGBIG2; ch[mf][f][1] = NEGBIG2;
                            }
                        }
                    }
                }
                #pragma unroll
                for (int mf = 0; mf < 2; mf++)
                    #pragma unroll
                    for (int f = 0; f < 2; f++) {
                        ph[mf][p * 2 + f][0] = h2ex2(ch[mf][f][0]);
                        ph[mf][p * 2 + f][1] = h2ex2(ch[mf][f][1]);
                    }
            }
            // O += P V ; l += P @ ones  (fp32 accumulate)
            #pragma unroll
            for (int kk = 0; kk < 4; kk++) {
                #pragma unroll
                for (int mf = 0; mf < 2; mf++)
                    mma16816(lacc[mf], ph[mf][2 * kk][0], ph[mf][2 * kk][1],
                             ph[mf][2 * kk + 1][0], ph[mf][2 * kk + 1][1], ONES2, ONES2);
                #pragma unroll
                for (int p = 0; p < 2; p++) {
                    unsigned bb0, bb1, bb2, bb3;
                    unsigned addr = sm_u32(&Vt[buf][(p * 16 + (lane & 15)) * 136
                                           + (half * 4 + kk) * 16 + ((lane >> 4) << 3)]);
                    ldsm4(addr, bb0, bb1, bb2, bb3);
                    #pragma unroll
                    for (int mf = 0; mf < 2; mf++) {
                        mma16816(oacc[mf][2 * p],     ph[mf][2 * kk][0], ph[mf][2 * kk][1],
                                 ph[mf][2 * kk + 1][0], ph[mf][2 * kk + 1][1], bb0, bb2);
                        mma16816(oacc[mf][2 * p + 1], ph[mf][2 * kk][0], ph[mf][2 * kk][1],
                                 ph[mf][2 * kk + 1][0], ph[mf][2 * kk + 1][1], bb1, bb3);
                    }
                }
            }
        }
        __syncthreads();
    }

    #pragma unroll
    for (int mf = 0; mf < 2; mf++) {
        float inv0 = 1.f / lacc[mf][0];
        float inv1 = 1.f / lacc[mf][2];
        int r = n0 + w * 32 + mf * 16 + (lane >> 2);
        #pragma unroll
        for (int nf = 0; nf < 4; nf++) {
            int d = h * 32 + nf * 8 + (lane & 3) * 2;
            if (r < N_) {
                *(float2*)(out + ((size_t)(b * N_ + r)) * C_ + d) =
                    make_float2(oacc[mf][nf][0] * inv0, oacc[mf][nf][1] * inv0);
            }
            if (r + 8 < N_) {
                *(float2*)(out + ((size_t)(b * N_ + r + 8)) * C_ + d) =
                    make_float2(oacc[mf][nf][2] * inv1, oacc[mf][nf][3] * inv1);
            }
        }
    }
}

// ---------------------------------------------------------------------------
extern "C" void kernel_launch(void* const* d_in, const int* in_sizes, int n_in,
                              void* d_out, int out_size) {
    (void)in_sizes; (void)n_in; (void)out_size;
    const float* x     = (const float*)d_in[0];
    const float* Wq    = (const float*)d_in[1];
    const float* bq    = (const float*)d_in[2];
    const float* Wk    = (const float*)d_in[3];
    const float* bk    = (const float*)d_in[4];
    const float* Wv    = (const float*)d_in[5];
    const float* bv    = (const float*)d_in[6];
    const float* Wc    = (const float*)d_in[7];
    const float* gamma = (const float*)d_in[9];
    const float* beta  = (const float*)d_in[10];
    float* out = (float*)d_out;

    static bool attr_done = false;
    if (!attr_done) {
        cudaFuncSetAttribute(k_red_projQ, cudaFuncAttributeMaxDynamicSharedMemorySize,
                             RED_SMEM);
        attr_done = true;
    }

    k_pre<<<TRX_CTAS + 384, 256>>>(x, Wq, Wk, Wv);
    k_red_projQ<<<RED_CTAS + PQ_CTAS, 256, RED_SMEM>>>(Wc, x, bq);
    k_ln<<<B_ * M_ / 8, 256>>>(gamma, beta);
    k_projKV<<<2 * KV_CTAS, 256>>>(bk, bv);
    dim3 ga((N_ + 127) / 128, H_, B_);
    k_attn<<<ga, 128>>>(out);
}